// round 1
// baseline (speedup 1.0000x reference)
#include <cuda_runtime.h>
#include <cuda_bf16.h>
#include <math.h>

#define CCH 180
#define FCD 540           // 3*C
#define HID 1620          // 3*FC
#define NGR 2048
#define LNUM 6
#define MAXN 50000
#define MAXE 150000

// ---------------- scratch (device globals; no allocation allowed) ----------------
__device__ float g_h  [MAXN * CCH];
__device__ float g_m  [MAXN * CCH];
__device__ float g_agg[MAXN * CCH];
__device__ float g_gi [MAXN * FCD];
__device__ float g_gh [MAXN * FCD];
__device__ float g_pool[NGR * FCD];
__device__ float g_cnt [3 * NGR];
__device__ float g_x  [NGR * FCD];
__device__ float g_b1 [NGR * HID];
__device__ float g_b2 [NGR * HID];

// ---------------- generic tiled SGEMM ----------------
// C[n,m] = sum_k A[n,k] * (TRANSB ? B[m,k] : B[k,m])  (+bias[m]) (+relu)
template<int TRANSB, int RELU, int BIAS>
__global__ __launch_bounds__(256)
void gemm_kernel(const float* __restrict__ A, const float* __restrict__ B,
                 const float* __restrict__ bias, float* __restrict__ C,
                 int N, int K, int M)
{
    __shared__ float As[16][65];
    __shared__ float Bs[16][65];
    const int tx = threadIdx.x & 15;
    const int ty = threadIdx.x >> 4;
    const int n0 = blockIdx.x * 64;
    const int m0 = blockIdx.y * 64;

    float acc[4][4];
    #pragma unroll
    for (int i = 0; i < 4; i++)
        #pragma unroll
        for (int j = 0; j < 4; j++) acc[i][j] = 0.f;

    for (int k0 = 0; k0 < K; k0 += 16) {
        // load A tile: 64 rows x 16 k
        #pragma unroll
        for (int i = 0; i < 4; i++) {
            int idx = threadIdx.x + i * 256;
            int r = idx >> 4, c = idx & 15;
            int gr = n0 + r, gc = k0 + c;
            As[c][r] = (gr < N && gc < K) ? A[(size_t)gr * K + gc] : 0.f;
        }
        // load B tile: Bs[k][m]
        #pragma unroll
        for (int i = 0; i < 4; i++) {
            int idx = threadIdx.x + i * 256;
            if (TRANSB) {
                int mm = idx >> 4, c = idx & 15;
                int gm = m0 + mm, gc = k0 + c;
                Bs[c][mm] = (gm < M && gc < K) ? B[(size_t)gm * K + gc] : 0.f;
            } else {
                int c = idx >> 6, mm = idx & 63;
                int gc = k0 + c, gm = m0 + mm;
                Bs[c][mm] = (gc < K && gm < M) ? B[(size_t)gc * M + gm] : 0.f;
            }
        }
        __syncthreads();
        #pragma unroll
        for (int kk = 0; kk < 16; kk++) {
            float a[4], b[4];
            #pragma unroll
            for (int i = 0; i < 4; i++) a[i] = As[kk][ty * 4 + i];
            #pragma unroll
            for (int j = 0; j < 4; j++) b[j] = Bs[kk][tx * 4 + j];
            #pragma unroll
            for (int i = 0; i < 4; i++)
                #pragma unroll
                for (int j = 0; j < 4; j++)
                    acc[i][j] += a[i] * b[j];
        }
        __syncthreads();
    }

    #pragma unroll
    for (int i = 0; i < 4; i++) {
        int r = n0 + ty * 4 + i;
        if (r >= N) continue;
        #pragma unroll
        for (int j = 0; j < 4; j++) {
            int mcol = m0 + tx * 4 + j;
            if (mcol >= M) continue;
            float v = acc[i][j];
            if (BIAS) v += bias[mcol];
            if (RELU) v = fmaxf(v, 0.f);
            C[(size_t)r * M + mcol] = v;
        }
    }
}

// ---------------- elementwise / graph kernels ----------------
__global__ void pad_kernel(const float* __restrict__ x, float* __restrict__ h, int N, int F)
{
    int i = blockIdx.x * blockDim.x + threadIdx.x;
    if (i >= N * CCH) return;
    int n = i / CCH, c = i - n * CCH;
    h[i] = (c < F) ? x[(size_t)n * F + c] : 0.f;
}

__global__ void zero_kernel(float* __restrict__ p, int n)
{
    int i = blockIdx.x * blockDim.x + threadIdx.x;
    if (i < n) p[i] = 0.f;
}

// agg[dst] += m[src], 45 float4 chunks per edge
__global__ void scatter_kernel(const float* __restrict__ msg, const int* __restrict__ ei,
                               float* __restrict__ agg, int E)
{
    int i = blockIdx.x * blockDim.x + threadIdx.x;
    if (i >= E * 45) return;
    int e = i / 45, c = i - e * 45;
    int src = ei[e];
    int dst = ei[E + e];
    float4 v = reinterpret_cast<const float4*>(msg + (size_t)src * CCH)[c];
    float* p = agg + (size_t)dst * CCH + c * 4;
    atomicAdd(p + 0, v.x);
    atomicAdd(p + 1, v.y);
    atomicAdd(p + 2, v.z);
    atomicAdd(p + 3, v.w);
}

__global__ void gate_kernel(const float* __restrict__ gi, const float* __restrict__ gh,
                            float* __restrict__ h, int N)
{
    int i = blockIdx.x * blockDim.x + threadIdx.x;
    if (i >= N * CCH) return;
    int n = i / CCH, c = i - n * CCH;
    const float* pi = gi + (size_t)n * FCD;
    const float* ph = gh + (size_t)n * FCD;
    float ir = pi[c], iz = pi[c + CCH], in = pi[c + 2 * CCH];
    float hr = ph[c], hz = ph[c + CCH], hn = ph[c + 2 * CCH];
    float r  = 1.f / (1.f + expf(-(ir + hr)));
    float z  = 1.f / (1.f + expf(-(iz + hz)));
    float nn = tanhf(in + r * hn);
    float ho = h[i];
    h[i] = (1.f - z) * nn + z * ho;
}

__global__ void count_kernel(const int* __restrict__ batch, float* __restrict__ cnt, int N)
{
    int i = blockIdx.x * blockDim.x + threadIdx.x;
    if (i < N) atomicAdd(&cnt[batch[i]], 1.f);
}

// pooled[b, comp*180 + c] += relu(h[n,c])
__global__ void pool_kernel(const float* __restrict__ h, const int* __restrict__ batch,
                            float* __restrict__ pool, int comp, int N)
{
    int i = blockIdx.x * blockDim.x + threadIdx.x;
    if (i >= N * CCH) return;
    int n = i / CCH, c = i - n * CCH;
    float v = fmaxf(h[i], 0.f);
    atomicAdd(&pool[(size_t)batch[n] * FCD + comp * CCH + c], v);
}

// mean + batchnorm (eval)
__global__ void bn_kernel(const float* __restrict__ pool, const float* __restrict__ cnt,
                          const float* __restrict__ gamma, const float* __restrict__ beta,
                          const float* __restrict__ mean, const float* __restrict__ var,
                          float* __restrict__ xout)
{
    int i = blockIdx.x * blockDim.x + threadIdx.x;
    if (i >= NGR * FCD) return;
    int b = i / FCD, j = i - b * FCD;
    int comp = j / CCH;
    float cn = fmaxf(cnt[comp * NGR + b], 1.f);
    float v = pool[i] / cn;
    v = (v - mean[j]) * rsqrtf(var[j] + 1e-5f) * gamma[j] + beta[j];
    xout[i] = v;
}

// ---------------- host orchestration ----------------
static inline void launch_gemm_nn(const float* A, const float* B, float* C,
                                  int N, int K, int M, cudaStream_t s)
{
    dim3 grid((N + 63) / 64, (M + 63) / 64);
    gemm_kernel<0, 0, 0><<<grid, 256, 0, s>>>(A, B, nullptr, C, N, K, M);
}
template<int RELU>
static inline void launch_gemm_nt_bias(const float* A, const float* B, const float* bias,
                                       float* C, int N, int K, int M, cudaStream_t s)
{
    dim3 grid((N + 63) / 64, (M + 63) / 64);
    gemm_kernel<1, RELU, 1><<<grid, 256, 0, s>>>(A, B, bias, C, N, K, M);
}

extern "C" void kernel_launch(void* const* d_in, const int* in_sizes, int n_in,
                              void* d_out, int out_size)
{
    cudaStream_t s = 0;

    const float* x[3]     = {(const float*)d_in[0], (const float*)d_in[3], (const float*)d_in[6]};
    const int*   ei[3]    = {(const int*)d_in[1], (const int*)d_in[4], (const int*)d_in[7]};
    const int*   batch[3] = {(const int*)d_in[2], (const int*)d_in[5], (const int*)d_in[8]};
    const float* convW = (const float*)d_in[9];
    const float* Wih   = (const float*)d_in[10];
    const float* Whh   = (const float*)d_in[11];
    const float* bih   = (const float*)d_in[12];
    const float* bhh   = (const float*)d_in[13];
    const float* bn_g  = (const float*)d_in[14];
    const float* bn_b  = (const float*)d_in[15];
    const float* bn_m  = (const float*)d_in[16];
    const float* bn_v  = (const float*)d_in[17];
    const float* fc1W  = (const float*)d_in[18];
    const float* fc1b  = (const float*)d_in[19];
    const float* fc2W  = (const float*)d_in[20];
    const float* fc2b  = (const float*)d_in[21];
    const float* fc25W = (const float*)d_in[22];
    const float* fc25b = (const float*)d_in[23];
    const float* fc3W  = (const float*)d_in[24];
    const float* fc3b  = (const float*)d_in[25];

    const int N = in_sizes[2];          // nodes per component (50000)
    const int E = in_sizes[1] / 2;      // edges (150000)
    const int F = in_sizes[0] / N;      // input feat dim (64)

    float *h_, *m_, *agg_, *gi_, *gh_, *pool_, *cnt_, *x_, *b1_, *b2_;
    cudaGetSymbolAddress((void**)&h_,   g_h);
    cudaGetSymbolAddress((void**)&m_,   g_m);
    cudaGetSymbolAddress((void**)&agg_, g_agg);
    cudaGetSymbolAddress((void**)&gi_,  g_gi);
    cudaGetSymbolAddress((void**)&gh_,  g_gh);
    cudaGetSymbolAddress((void**)&pool_,g_pool);
    cudaGetSymbolAddress((void**)&cnt_, g_cnt);
    cudaGetSymbolAddress((void**)&x_,   g_x);
    cudaGetSymbolAddress((void**)&b1_,  g_b1);
    cudaGetSymbolAddress((void**)&b2_,  g_b2);

    const int TPB = 256;
    const int nNC   = N * CCH;
    const int gNC   = (nNC + TPB - 1) / TPB;
    const int gScat = (E * 45 + TPB - 1) / TPB;

    // clear pooled accumulators
    zero_kernel<<<(NGR * FCD + TPB - 1) / TPB, TPB, 0, s>>>(pool_, NGR * FCD);
    zero_kernel<<<(3 * NGR + TPB - 1) / TPB, TPB, 0, s>>>(cnt_, 3 * NGR);

    for (int comp = 0; comp < 3; comp++) {
        pad_kernel<<<gNC, TPB, 0, s>>>(x[comp], h_, N, F);
        const float* WihC = Wih + (size_t)comp * FCD * CCH;
        const float* WhhC = Whh + (size_t)comp * FCD * CCH;
        const float* bihC = bih + (size_t)comp * FCD;
        const float* bhhC = bhh + (size_t)comp * FCD;

        for (int l = 0; l < LNUM; l++) {
            const float* Wl = convW + ((size_t)comp * LNUM + l) * CCH * CCH;
            // m = h @ Wl
            launch_gemm_nn(h_, Wl, m_, N, CCH, CCH, s);
            // agg = scatter_add(m[src] -> dst)
            zero_kernel<<<gNC, TPB, 0, s>>>(agg_, nNC);
            scatter_kernel<<<gScat, TPB, 0, s>>>(m_, ei[comp], agg_, E);
            // gi = agg @ Wih^T + bih ; gh = h @ Whh^T + bhh
            launch_gemm_nt_bias<0>(agg_, WihC, bihC, gi_, N, CCH, FCD, s);
            launch_gemm_nt_bias<0>(h_,  WhhC, bhhC, gh_, N, CCH, FCD, s);
            // GRU gate update (in place on h)
            gate_kernel<<<gNC, TPB, 0, s>>>(gi_, gh_, h_, N);
        }
        count_kernel<<<(N + TPB - 1) / TPB, TPB, 0, s>>>(batch[comp], cnt_ + comp * NGR, N);
        pool_kernel<<<gNC, TPB, 0, s>>>(h_, batch[comp], pool_, comp, N);
    }

    // mean-pool + batchnorm
    bn_kernel<<<(NGR * FCD + TPB - 1) / TPB, TPB, 0, s>>>(pool_, cnt_, bn_g, bn_b, bn_m, bn_v, x_);

    // MLP head
    launch_gemm_nt_bias<1>(x_,  fc1W,  fc1b,  b1_, NGR, FCD, HID, s);
    launch_gemm_nt_bias<1>(b1_, fc2W,  fc2b,  b2_, NGR, HID, HID, s);
    launch_gemm_nt_bias<1>(b2_, fc25W, fc25b, x_,  NGR, HID, FCD, s);
    launch_gemm_nt_bias<0>(x_,  fc3W,  fc3b,  (float*)d_out, NGR, FCD, 3, s);
}

// round 2
// speedup vs baseline: 2.5430x; 2.5430x over previous
#include <cuda_runtime.h>
#include <cuda_bf16.h>
#include <math.h>
#include <stdint.h>

#define CCH 180
#define FCD 540           // 3*C
#define HID 1620          // 3*FC
#define NGR 2048
#define LNUM 6
#define MAXN 50000
#define MAXE 150000

// ---------------- scratch (device globals; no allocation allowed) ----------------
__device__ float g_h  [MAXN * CCH];
__device__ float g_m  [MAXN * CCH];
__device__ float g_agg[MAXN * CCH];
__device__ float g_gi [MAXN * FCD];
__device__ float g_gh [MAXN * FCD];
__device__ float g_pool[NGR * FCD];
__device__ float g_cnt [3 * NGR];
__device__ float g_x  [NGR * FCD];
__device__ float g_b1 [NGR * HID];
__device__ float g_b2 [NGR * HID];

// ---------------- tf32 tensor-core GEMM ----------------
__device__ __forceinline__ uint32_t f2tf32(float f) {
    uint32_t u;
    asm("cvt.rna.tf32.f32 %0, %1;" : "=r"(u) : "f"(f));
    return u;
}

__device__ __forceinline__ void mma_tf32(float* c, const uint32_t* a, const uint32_t* b) {
    asm volatile(
        "mma.sync.aligned.m16n8k8.row.col.f32.tf32.tf32.f32 "
        "{%0,%1,%2,%3}, {%4,%5,%6,%7}, {%8,%9}, {%0,%1,%2,%3};"
        : "+f"(c[0]), "+f"(c[1]), "+f"(c[2]), "+f"(c[3])
        : "r"(a[0]), "r"(a[1]), "r"(a[2]), "r"(a[3]), "r"(b[0]), "r"(b[1]));
}

// C[n,m] = sum_k A[n,k] * (TRANSB ? B[m,k] : B[k,m])  (+bias[m]) (+relu)
// Block tile: 128 (rows) x 64 (cols), K-tile 16. 8 warps: 2 (row) x 4 (col),
// warp tile 64x16 -> 4 m16-tiles x 2 n8-tiles per k8 step.
template<int TRANSB, int RELU, int BIAS>
__global__ __launch_bounds__(256)
void gemm_tf32(const float* __restrict__ A, const float* __restrict__ B,
               const float* __restrict__ bias, float* __restrict__ C,
               int N, int K, int M)
{
    __shared__ uint32_t As[16][134];   // [k][m], pad 134 -> conflict-light reads
    __shared__ uint32_t Bs[16][72];    // [k][n], pad 72  -> conflict-free reads

    const int tid  = threadIdx.x;
    const int lane = tid & 31;
    const int wid  = tid >> 5;
    const int wm   = (wid & 1) * 64;
    const int wn   = (wid >> 1) * 16;
    const int n0   = blockIdx.x * 128;
    const int m0   = blockIdx.y * 64;

    float acc[4][2][4];
    #pragma unroll
    for (int i = 0; i < 4; i++)
        #pragma unroll
        for (int j = 0; j < 2; j++)
            #pragma unroll
            for (int q = 0; q < 4; q++) acc[i][j][q] = 0.f;

    const int ar = tid >> 2;          // A row within tile (0..63, +64)
    const int ak = (tid & 3) * 4;     // A k quad base

    float4 pa0, pa1, pb;

    auto loadA = [&](int k0) {
        int gk = k0 + ak;
        int g0 = n0 + ar, g1 = g0 + 64;
        pa0 = make_float4(0.f, 0.f, 0.f, 0.f);
        pa1 = make_float4(0.f, 0.f, 0.f, 0.f);
        if (gk < K) {   // K is always a multiple of 4 here
            if (g0 < N) pa0 = *reinterpret_cast<const float4*>(A + (size_t)g0 * K + gk);
            if (g1 < N) pa1 = *reinterpret_cast<const float4*>(A + (size_t)g1 * K + gk);
        }
    };
    auto loadB = [&](int k0) {
        pb = make_float4(0.f, 0.f, 0.f, 0.f);
        if (TRANSB) {
            int m = tid >> 2, gk = k0 + (tid & 3) * 4;
            int gm = m0 + m;
            if (gm < M && gk < K)
                pb = *reinterpret_cast<const float4*>(B + (size_t)gm * K + gk);
        } else {
            int kk = tid >> 4, mq = (tid & 15) * 4;
            int gk = k0 + kk, gm = m0 + mq;
            if (gk < K) {
                if (gm + 3 < M) {
                    pb = *reinterpret_cast<const float4*>(B + (size_t)gk * M + gm);
                } else {
                    if (gm     < M) pb.x = B[(size_t)gk * M + gm];
                    if (gm + 1 < M) pb.y = B[(size_t)gk * M + gm + 1];
                    if (gm + 2 < M) pb.z = B[(size_t)gk * M + gm + 2];
                }
            }
        }
    };
    auto storeT = [&]() {
        As[ak + 0][ar] = f2tf32(pa0.x);
        As[ak + 1][ar] = f2tf32(pa0.y);
        As[ak + 2][ar] = f2tf32(pa0.z);
        As[ak + 3][ar] = f2tf32(pa0.w);
        As[ak + 0][ar + 64] = f2tf32(pa1.x);
        As[ak + 1][ar + 64] = f2tf32(pa1.y);
        As[ak + 2][ar + 64] = f2tf32(pa1.z);
        As[ak + 3][ar + 64] = f2tf32(pa1.w);
        if (TRANSB) {
            int m = tid >> 2, kq = (tid & 3) * 4;
            Bs[kq + 0][m] = f2tf32(pb.x);
            Bs[kq + 1][m] = f2tf32(pb.y);
            Bs[kq + 2][m] = f2tf32(pb.z);
            Bs[kq + 3][m] = f2tf32(pb.w);
        } else {
            int kk = tid >> 4, mq = (tid & 15) * 4;
            Bs[kk][mq + 0] = f2tf32(pb.x);
            Bs[kk][mq + 1] = f2tf32(pb.y);
            Bs[kk][mq + 2] = f2tf32(pb.z);
            Bs[kk][mq + 3] = f2tf32(pb.w);
        }
    };
    auto compute = [&]() {
        #pragma unroll
        for (int ks = 0; ks < 16; ks += 8) {
            uint32_t a[4][4], b[2][2];
            int kb = ks + (lane & 3);
            int rr = lane >> 2;
            #pragma unroll
            for (int i = 0; i < 4; i++) {
                int r = wm + i * 16 + rr;
                a[i][0] = As[kb][r];
                a[i][1] = As[kb][r + 8];
                a[i][2] = As[kb + 4][r];
                a[i][3] = As[kb + 4][r + 8];
            }
            #pragma unroll
            for (int j = 0; j < 2; j++) {
                int c = wn + j * 8 + rr;
                b[j][0] = Bs[kb][c];
                b[j][1] = Bs[kb + 4][c];
            }
            #pragma unroll
            for (int i = 0; i < 4; i++)
                #pragma unroll
                for (int j = 0; j < 2; j++)
                    mma_tf32(acc[i][j], a[i], b[j]);
        }
    };

    loadA(0); loadB(0);
    storeT();
    __syncthreads();
    for (int k0 = 16; k0 < K; k0 += 16) {
        loadA(k0); loadB(k0);   // prefetch next tile to regs
        compute();              // compute on smem tile
        __syncthreads();
        storeT();
        __syncthreads();
    }
    compute();

    // epilogue
    #pragma unroll
    for (int i = 0; i < 4; i++) {
        #pragma unroll
        for (int j = 0; j < 2; j++) {
            int r0 = n0 + wm + i * 16 + (lane >> 2);
            int c0 = m0 + wn + j * 8 + (lane & 3) * 2;
            if (c0 >= M) continue;
            bool c1ok = (c0 + 1) < M;
            float bv0 = BIAS ? bias[c0] : 0.f;
            float bv1 = (BIAS && c1ok) ? bias[c0 + 1] : 0.f;
            #pragma unroll
            for (int hrow = 0; hrow < 2; hrow++) {
                int r = r0 + hrow * 8;
                if (r >= N) continue;
                float v0 = acc[i][j][hrow * 2 + 0] + bv0;
                float v1 = acc[i][j][hrow * 2 + 1] + bv1;
                if (RELU) { v0 = fmaxf(v0, 0.f); v1 = fmaxf(v1, 0.f); }
                if (c1ok && ((M & 1) == 0)) {
                    *reinterpret_cast<float2*>(C + (size_t)r * M + c0) = make_float2(v0, v1);
                } else {
                    C[(size_t)r * M + c0] = v0;
                    if (c1ok) C[(size_t)r * M + c0 + 1] = v1;
                }
            }
        }
    }
}

// ---------------- elementwise / graph kernels ----------------
__global__ void pad_kernel(const float* __restrict__ x, float* __restrict__ h, int N, int F)
{
    int i = blockIdx.x * blockDim.x + threadIdx.x;
    if (i >= N * CCH) return;
    int n = i / CCH, c = i - n * CCH;
    h[i] = (c < F) ? x[(size_t)n * F + c] : 0.f;
}

__global__ void zero_kernel(float* __restrict__ p, int n)
{
    int i = blockIdx.x * blockDim.x + threadIdx.x;
    if (i < n) p[i] = 0.f;
}

// agg[dst] += m[src], 45 float4 chunks per edge, vectorized reduction (no return)
__global__ void scatter_kernel(const float* __restrict__ msg, const int* __restrict__ ei,
                               float* __restrict__ agg, int E)
{
    int i = blockIdx.x * blockDim.x + threadIdx.x;
    if (i >= E * 45) return;
    int e = i / 45, c = i - e * 45;
    int src = ei[e];
    int dst = ei[E + e];
    float4 v = reinterpret_cast<const float4*>(msg + (size_t)src * CCH)[c];
    float* p = agg + (size_t)dst * CCH + c * 4;
    asm volatile("red.global.add.v4.f32 [%0], {%1,%2,%3,%4};"
                 :: "l"(p), "f"(v.x), "f"(v.y), "f"(v.z), "f"(v.w) : "memory");
}

__global__ void gate_kernel(const float* __restrict__ gi, const float* __restrict__ gh,
                            float* __restrict__ h, int N)
{
    int i = blockIdx.x * blockDim.x + threadIdx.x;
    if (i >= N * CCH) return;
    int n = i / CCH, c = i - n * CCH;
    const float* pi = gi + (size_t)n * FCD;
    const float* ph = gh + (size_t)n * FCD;
    float ir = pi[c], iz = pi[c + CCH], in = pi[c + 2 * CCH];
    float hr = ph[c], hz = ph[c + CCH], hn = ph[c + 2 * CCH];
    float r  = 1.f / (1.f + expf(-(ir + hr)));
    float z  = 1.f / (1.f + expf(-(iz + hz)));
    float nn = tanhf(in + r * hn);
    float ho = h[i];
    h[i] = (1.f - z) * nn + z * ho;
}

__global__ void count_kernel(const int* __restrict__ batch, float* __restrict__ cnt, int N)
{
    int i = blockIdx.x * blockDim.x + threadIdx.x;
    if (i < N) atomicAdd(&cnt[batch[i]], 1.f);
}

// pooled[b, comp*180 + c] += relu(h[n,c])
__global__ void pool_kernel(const float* __restrict__ h, const int* __restrict__ batch,
                            float* __restrict__ pool, int comp, int N)
{
    int i = blockIdx.x * blockDim.x + threadIdx.x;
    if (i >= N * CCH) return;
    int n = i / CCH, c = i - n * CCH;
    float v = fmaxf(h[i], 0.f);
    atomicAdd(&pool[(size_t)batch[n] * FCD + comp * CCH + c], v);
}

// mean + batchnorm (eval)
__global__ void bn_kernel(const float* __restrict__ pool, const float* __restrict__ cnt,
                          const float* __restrict__ gamma, const float* __restrict__ beta,
                          const float* __restrict__ mean, const float* __restrict__ var,
                          float* __restrict__ xout)
{
    int i = blockIdx.x * blockDim.x + threadIdx.x;
    if (i >= NGR * FCD) return;
    int b = i / FCD, j = i - b * FCD;
    int comp = j / CCH;
    float cn = fmaxf(cnt[comp * NGR + b], 1.f);
    float v = pool[i] / cn;
    v = (v - mean[j]) * rsqrtf(var[j] + 1e-5f) * gamma[j] + beta[j];
    xout[i] = v;
}

// ---------------- host orchestration ----------------
static inline void launch_gemm_nn(const float* A, const float* B, float* C,
                                  int N, int K, int M, cudaStream_t s)
{
    dim3 grid((N + 127) / 128, (M + 63) / 64);
    gemm_tf32<0, 0, 0><<<grid, 256, 0, s>>>(A, B, nullptr, C, N, K, M);
}
template<int RELU>
static inline void launch_gemm_nt_bias(const float* A, const float* B, const float* bias,
                                       float* C, int N, int K, int M, cudaStream_t s)
{
    dim3 grid((N + 127) / 128, (M + 63) / 64);
    gemm_tf32<1, RELU, 1><<<grid, 256, 0, s>>>(A, B, bias, C, N, K, M);
}

extern "C" void kernel_launch(void* const* d_in, const int* in_sizes, int n_in,
                              void* d_out, int out_size)
{
    cudaStream_t s = 0;

    const float* x[3]     = {(const float*)d_in[0], (const float*)d_in[3], (const float*)d_in[6]};
    const int*   ei[3]    = {(const int*)d_in[1], (const int*)d_in[4], (const int*)d_in[7]};
    const int*   batch[3] = {(const int*)d_in[2], (const int*)d_in[5], (const int*)d_in[8]};
    const float* convW = (const float*)d_in[9];
    const float* Wih   = (const float*)d_in[10];
    const float* Whh   = (const float*)d_in[11];
    const float* bih   = (const float*)d_in[12];
    const float* bhh   = (const float*)d_in[13];
    const float* bn_g  = (const float*)d_in[14];
    const float* bn_b  = (const float*)d_in[15];
    const float* bn_m  = (const float*)d_in[16];
    const float* bn_v  = (const float*)d_in[17];
    const float* fc1W  = (const float*)d_in[18];
    const float* fc1b  = (const float*)d_in[19];
    const float* fc2W  = (const float*)d_in[20];
    const float* fc2b  = (const float*)d_in[21];
    const float* fc25W = (const float*)d_in[22];
    const float* fc25b = (const float*)d_in[23];
    const float* fc3W  = (const float*)d_in[24];
    const float* fc3b  = (const float*)d_in[25];

    const int N = in_sizes[2];          // nodes per component (50000)
    const int E = in_sizes[1] / 2;      // edges (150000)
    const int F = in_sizes[0] / N;      // input feat dim (64)

    float *h_, *m_, *agg_, *gi_, *gh_, *pool_, *cnt_, *x_, *b1_, *b2_;
    cudaGetSymbolAddress((void**)&h_,   g_h);
    cudaGetSymbolAddress((void**)&m_,   g_m);
    cudaGetSymbolAddress((void**)&agg_, g_agg);
    cudaGetSymbolAddress((void**)&gi_,  g_gi);
    cudaGetSymbolAddress((void**)&gh_,  g_gh);
    cudaGetSymbolAddress((void**)&pool_,g_pool);
    cudaGetSymbolAddress((void**)&cnt_, g_cnt);
    cudaGetSymbolAddress((void**)&x_,   g_x);
    cudaGetSymbolAddress((void**)&b1_,  g_b1);
    cudaGetSymbolAddress((void**)&b2_,  g_b2);

    const int TPB = 256;
    const int nNC   = N * CCH;
    const int gNC   = (nNC + TPB - 1) / TPB;
    const int gScat = (E * 45 + TPB - 1) / TPB;

    // clear pooled accumulators
    zero_kernel<<<(NGR * FCD + TPB - 1) / TPB, TPB, 0, s>>>(pool_, NGR * FCD);
    zero_kernel<<<(3 * NGR + TPB - 1) / TPB, TPB, 0, s>>>(cnt_, 3 * NGR);

    for (int comp = 0; comp < 3; comp++) {
        pad_kernel<<<gNC, TPB, 0, s>>>(x[comp], h_, N, F);
        const float* WihC = Wih + (size_t)comp * FCD * CCH;
        const float* WhhC = Whh + (size_t)comp * FCD * CCH;
        const float* bihC = bih + (size_t)comp * FCD;
        const float* bhhC = bhh + (size_t)comp * FCD;

        for (int l = 0; l < LNUM; l++) {
            const float* Wl = convW + ((size_t)comp * LNUM + l) * CCH * CCH;
            // m = h @ Wl
            launch_gemm_nn(h_, Wl, m_, N, CCH, CCH, s);
            // agg = scatter_add(m[src] -> dst)
            zero_kernel<<<gNC, TPB, 0, s>>>(agg_, nNC);
            scatter_kernel<<<gScat, TPB, 0, s>>>(m_, ei[comp], agg_, E);
            // gi = agg @ Wih^T + bih ; gh = h @ Whh^T + bhh
            launch_gemm_nt_bias<0>(agg_, WihC, bihC, gi_, N, CCH, FCD, s);
            launch_gemm_nt_bias<0>(h_,  WhhC, bhhC, gh_, N, CCH, FCD, s);
            // GRU gate update (in place on h)
            gate_kernel<<<gNC, TPB, 0, s>>>(gi_, gh_, h_, N);
        }
        count_kernel<<<(N + TPB - 1) / TPB, TPB, 0, s>>>(batch[comp], cnt_ + comp * NGR, N);
        pool_kernel<<<gNC, TPB, 0, s>>>(h_, batch[comp], pool_, comp, N);
    }

    // mean-pool + batchnorm
    bn_kernel<<<(NGR * FCD + TPB - 1) / TPB, TPB, 0, s>>>(pool_, cnt_, bn_g, bn_b, bn_m, bn_v, x_);

    // MLP head
    launch_gemm_nt_bias<1>(x_,  fc1W,  fc1b,  b1_, NGR, FCD, HID, s);
    launch_gemm_nt_bias<1>(b1_, fc2W,  fc2b,  b2_, NGR, HID, HID, s);
    launch_gemm_nt_bias<1>(b2_, fc25W, fc25b, x_,  NGR, HID, FCD, s);
    launch_gemm_nt_bias<0>(x_,  fc3W,  fc3b,  (float*)d_out, NGR, FCD, 3, s);
}

// round 3
// speedup vs baseline: 3.3124x; 1.3026x over previous
#include <cuda_runtime.h>
#include <cuda_bf16.h>
#include <math.h>
#include <stdint.h>

#define CCH 180
#define FCD 540           // 3*C
#define HID 1620          // 3*FC
#define NGR 2048
#define LNUM 6
#define MAXN 50000
#define MAXE 150000

// ---------------- scratch (device globals; no allocation allowed) ----------------
__device__ float g_h  [MAXN * CCH];
__device__ float g_m  [MAXN * CCH];
__device__ float g_agg[MAXN * CCH];
__device__ float g_gi [MAXN * FCD];
__device__ float g_gh [MAXN * FCD];
__device__ float g_pool[NGR * FCD];
__device__ float g_cnt [3 * NGR];
__device__ float g_x  [NGR * FCD];
__device__ float g_b1 [NGR * HID];
__device__ float g_b2 [NGR * HID];

// pre-converted (tf32-rounded) weights
#define OFF_CONV 0
#define OFF_WIH  972000
#define OFF_WHH  1263600
#define OFF_FC1  1555200
#define OFF_FC2  2430000
#define OFF_FC25 5054400
#define OFF_FC3  5929200
#define WTF_TOTAL 5930820
__device__ float g_wtf[WTF_TOTAL];

// ---------------- tf32 helpers ----------------
__device__ __forceinline__ uint32_t f2tf32(float f) {
    uint32_t u;
    asm("cvt.rna.tf32.f32 %0, %1;" : "=r"(u) : "f"(f));
    return u;
}

__device__ __forceinline__ void mma_tf32(float* c, const uint32_t* a, const uint32_t* b) {
    asm volatile(
        "mma.sync.aligned.m16n8k8.row.col.f32.tf32.tf32.f32 "
        "{%0,%1,%2,%3}, {%4,%5,%6,%7}, {%8,%9}, {%0,%1,%2,%3};"
        : "+f"(c[0]), "+f"(c[1]), "+f"(c[2]), "+f"(c[3])
        : "r"(a[0]), "r"(a[1]), "r"(a[2]), "r"(a[3]), "r"(b[0]), "r"(b[1]));
}

__device__ __forceinline__ void ldsm_x4(uint32_t& r0, uint32_t& r1, uint32_t& r2, uint32_t& r3,
                                        uint32_t saddr) {
    asm volatile("ldmatrix.sync.aligned.m8n8.x4.shared.b16 {%0,%1,%2,%3}, [%4];"
                 : "=r"(r0), "=r"(r1), "=r"(r2), "=r"(r3) : "r"(saddr));
}

__device__ __forceinline__ void cp_async16(uint32_t saddr, const void* gptr, int src_bytes) {
    asm volatile("cp.async.cg.shared.global [%0], [%1], 16, %2;"
                 :: "r"(saddr), "l"(gptr), "r"(src_bytes));
}
__device__ __forceinline__ void cp_commit() { asm volatile("cp.async.commit_group;"); }
__device__ __forceinline__ void cp_wait0()  { asm volatile("cp.async.wait_group 0;"); }

// ---------------- tf32 tensor-core GEMM v2 ----------------
// C[n,m] = sum_k A[n,k] * (TRANSB ? B[m,k] : B[k,m])  (+bias[m]) (+relu)
// A: f32 activations (converted to tf32 at smem store).
// B: pre-converted tf32 weights (raw copy).
// Block 128x64, k-tile 32, 8 warps (2 row x 4 col), warp 64x16.
// smem layouts [row][kchunk] with kchunk = 4 tf32 (16B), XOR swizzle kc^(row&7).
template<int TRANSB, int RELU, int BIAS>
__global__ __launch_bounds__(256)
void gemm_tf32(const float* __restrict__ A, const float* __restrict__ B,
               const float* __restrict__ bias, float* __restrict__ C,
               int N, int K, int M)
{
    __shared__ uint4 As4[2][128 * 8];   // 16KB / stage
    __shared__ uint4 Bs4[2][64 * 8];    // 8KB / stage

    const int tid  = threadIdx.x;
    const int lane = tid & 31;
    const int wid  = tid >> 5;
    const int wm   = (wid & 1) * 64;
    const int wn   = (wid >> 1) * 16;
    const int n0   = blockIdx.x * 128;
    const int m0   = blockIdx.y * 64;

    float acc[4][2][4];
    #pragma unroll
    for (int i = 0; i < 4; i++)
        #pragma unroll
        for (int j = 0; j < 2; j++)
            #pragma unroll
            for (int q = 0; q < 4; q++) acc[i][j][q] = 0.f;

    // ---- A loader: 128 rows x 8 chunks; thread -> row=tid>>1, chunks (tid&1)*4..+3
    const int arow = tid >> 1;
    const int ac0  = (tid & 1) * 4;
    const bool arow_ok = (n0 + arow) < N;
    const float* Ap = A + (size_t)(n0 + arow) * K;

    float4 pa[4];
    float4 pbnn[2];   // NN-path B staging regs

    auto loadA = [&](int k0) {
        #pragma unroll
        for (int c = 0; c < 4; c++) {
            int gk = k0 + (ac0 + c) * 4;
            pa[c] = make_float4(0.f, 0.f, 0.f, 0.f);
            if (arow_ok && gk < K)  // K % 4 == 0 -> full chunk valid
                pa[c] = *reinterpret_cast<const float4*>(Ap + gk);
        }
    };
    auto storeA = [&](int st) {
        #pragma unroll
        for (int c = 0; c < 4; c++) {
            int kc = ac0 + c;
            uint4 u;
            u.x = f2tf32(pa[c].x); u.y = f2tf32(pa[c].y);
            u.z = f2tf32(pa[c].z); u.w = f2tf32(pa[c].w);
            As4[st][(arow << 3) + (kc ^ (arow & 7))] = u;
        }
    };

    // ---- B loader
    auto issueB_nt = [&](int k0, int st) {   // B[m,k], raw tf32 copy via cp.async
        uint32_t sb = (uint32_t)__cvta_generic_to_shared(&Bs4[st][0]);
        #pragma unroll
        for (int i = 0; i < 2; i++) {
            int cid = tid * 2 + i;
            int m  = cid >> 3;
            int kc = cid & 7;
            int gm = m0 + m, gk = k0 + kc * 4;
            const float* gp = B + (size_t)gm * K + gk;
            int ok = (gm < M && gk < K) ? 16 : 0;
            cp_async16(sb + (((m << 3) + (kc ^ (m & 7))) << 4), gp, ok);
        }
    };
    auto loadB_nn = [&](int k0) {            // B[k,m] -> transpose via scalar LDG
        #pragma unroll
        for (int i = 0; i < 2; i++) {
            int s = tid + i * 256;           // s = kc*64 + m
            int kc = s >> 6, m = s & 63;
            int gm = m0 + m;
            float* d = &pbnn[i].x;
            #pragma unroll
            for (int q = 0; q < 4; q++) {
                int gk = k0 + kc * 4 + q;
                d[q] = (gm < M && gk < K) ? B[(size_t)gk * M + gm] : 0.f;
            }
        }
    };
    auto storeB_nn = [&](int st) {
        #pragma unroll
        for (int i = 0; i < 2; i++) {
            int s = tid + i * 256;
            int kc = s >> 6, m = s & 63;
            uint4 u;
            u.x = __float_as_uint(pbnn[i].x); u.y = __float_as_uint(pbnn[i].y);
            u.z = __float_as_uint(pbnn[i].z); u.w = __float_as_uint(pbnn[i].w);
            Bs4[st][(m << 3) + (kc ^ (m & 7))] = u;
        }
    };

    const int g  = lane >> 3;
    const int l7 = lane & 7;

    auto compute = [&](int st) {
        uint32_t aBase = (uint32_t)__cvta_generic_to_shared(&As4[st][0]);
        uint32_t bBase = (uint32_t)__cvta_generic_to_shared(&Bs4[st][0]);
        #pragma unroll
        for (int kb = 0; kb < 32; kb += 8) {
            const int kq = kb >> 2;
            uint32_t a[4][4];
            #pragma unroll
            for (int i = 0; i < 4; i++) {
                int row = wm + i * 16 + ((g & 1) << 3) + l7;
                int kc  = kq + (g >> 1);
                uint32_t ad = aBase + (((row << 3) + (kc ^ (row & 7))) << 4);
                ldsm_x4(a[i][0], a[i][1], a[i][2], a[i][3], ad);
            }
            uint32_t b[4];
            {
                int nrow = wn + ((g >> 1) << 3) + l7;
                int kc   = kq + (g & 1);
                uint32_t bd = bBase + (((nrow << 3) + (kc ^ (nrow & 7))) << 4);
                ldsm_x4(b[0], b[1], b[2], b[3], bd);
            }
            #pragma unroll
            for (int i = 0; i < 4; i++) {
                mma_tf32(acc[i][0], a[i], &b[0]);
                mma_tf32(acc[i][1], a[i], &b[2]);
            }
        }
    };

    const int T = (K + 31) / 32;

    // prologue: fill stage 0
    loadA(0);
    if (TRANSB) issueB_nt(0, 0); else loadB_nn(0);
    storeA(0);
    if (!TRANSB) storeB_nn(0);
    if (TRANSB) { cp_commit(); cp_wait0(); }
    __syncthreads();

    for (int kt = 0; kt < T; kt++) {
        const int cur = kt & 1, nxt = cur ^ 1;
        const bool more = (kt + 1) < T;
        if (more) {
            loadA((kt + 1) * 32);
            if (TRANSB) { issueB_nt((kt + 1) * 32, nxt); cp_commit(); }
            else loadB_nn((kt + 1) * 32);
        }
        compute(cur);
        if (more) {
            storeA(nxt);
            if (!TRANSB) storeB_nn(nxt);
            if (TRANSB) cp_wait0();
            __syncthreads();
        }
    }

    // epilogue
    #pragma unroll
    for (int i = 0; i < 4; i++) {
        #pragma unroll
        for (int j = 0; j < 2; j++) {
            int r0 = n0 + wm + i * 16 + (lane >> 2);
            int c0 = m0 + wn + j * 8 + (lane & 3) * 2;
            if (c0 >= M) continue;
            bool c1ok = (c0 + 1) < M;
            float bv0 = BIAS ? bias[c0] : 0.f;
            float bv1 = (BIAS && c1ok) ? bias[c0 + 1] : 0.f;
            #pragma unroll
            for (int hrow = 0; hrow < 2; hrow++) {
                int r = r0 + hrow * 8;
                if (r >= N) continue;
                float v0 = acc[i][j][hrow * 2 + 0] + bv0;
                float v1 = acc[i][j][hrow * 2 + 1] + bv1;
                if (RELU) { v0 = fmaxf(v0, 0.f); v1 = fmaxf(v1, 0.f); }
                if (c1ok && ((M & 1) == 0)) {
                    *reinterpret_cast<float2*>(C + (size_t)r * M + c0) = make_float2(v0, v1);
                } else {
                    C[(size_t)r * M + c0] = v0;
                    if (c1ok) C[(size_t)r * M + c0 + 1] = v1;
                }
            }
        }
    }
}

// ---------------- weight pre-conversion ----------------
__global__ void cvt_tf32_kernel(const float* __restrict__ in, float* __restrict__ out, int n)
{
    int i = blockIdx.x * blockDim.x + threadIdx.x;
    if (i < n) out[i] = __uint_as_float(f2tf32(in[i]));
}

// ---------------- elementwise / graph kernels ----------------
__global__ void pad_kernel(const float4* __restrict__ x, float4* __restrict__ h, int N, int F4)
{
    int i = blockIdx.x * blockDim.x + threadIdx.x;
    if (i >= N * 45) return;
    int n = i / 45, c = i - n * 45;
    float4 v = make_float4(0.f, 0.f, 0.f, 0.f);
    if (c < F4) v = x[(size_t)n * F4 + c];
    h[i] = v;
}

__global__ void zero_kernel(float4* __restrict__ p, int n4)
{
    int i = blockIdx.x * blockDim.x + threadIdx.x;
    if (i < n4) p[i] = make_float4(0.f, 0.f, 0.f, 0.f);
}

// agg[dst] += m[src], 45 float4 chunks per edge, vectorized reduction (no return)
__global__ void scatter_kernel(const float* __restrict__ msg, const int* __restrict__ ei,
                               float* __restrict__ agg, int E)
{
    int i = blockIdx.x * blockDim.x + threadIdx.x;
    if (i >= E * 45) return;
    int e = i / 45, c = i - e * 45;
    int src = ei[e];
    int dst = ei[E + e];
    float4 v = reinterpret_cast<const float4*>(msg + (size_t)src * CCH)[c];
    float* p = agg + (size_t)dst * CCH + c * 4;
    asm volatile("red.global.add.v4.f32 [%0], {%1,%2,%3,%4};"
                 :: "l"(p), "f"(v.x), "f"(v.y), "f"(v.z), "f"(v.w) : "memory");
}

__device__ __forceinline__ float sigm(float x) { return 1.f / (1.f + __expf(-x)); }

__global__ void gate_kernel(const float4* __restrict__ gi, const float4* __restrict__ gh,
                            float4* __restrict__ h, int N)
{
    int i = blockIdx.x * blockDim.x + threadIdx.x;
    if (i >= N * 45) return;
    int n = i / 45, c = i - n * 45;
    const float4* pi = gi + (size_t)n * 135;
    const float4* ph = gh + (size_t)n * 135;
    float4 ir = pi[c], iz = pi[c + 45], in4 = pi[c + 90];
    float4 hr = ph[c], hz = ph[c + 45], hn = ph[c + 90];
    float4 ho = h[i];
    float4 o;
    {
        float r = sigm(ir.x + hr.x), z = sigm(iz.x + hz.x);
        float nn = tanhf(in4.x + r * hn.x);
        o.x = (1.f - z) * nn + z * ho.x;
    }
    {
        float r = sigm(ir.y + hr.y), z = sigm(iz.y + hz.y);
        float nn = tanhf(in4.y + r * hn.y);
        o.y = (1.f - z) * nn + z * ho.y;
    }
    {
        float r = sigm(ir.z + hr.z), z = sigm(iz.z + hz.z);
        float nn = tanhf(in4.z + r * hn.z);
        o.z = (1.f - z) * nn + z * ho.z;
    }
    {
        float r = sigm(ir.w + hr.w), z = sigm(iz.w + hz.w);
        float nn = tanhf(in4.w + r * hn.w);
        o.w = (1.f - z) * nn + z * ho.w;
    }
    h[i] = o;
}

__global__ void count_kernel(const int* __restrict__ batch, float* __restrict__ cnt, int N)
{
    int i = blockIdx.x * blockDim.x + threadIdx.x;
    if (i < N) atomicAdd(&cnt[batch[i]], 1.f);
}

// pooled[b, comp*180 + c4*4..] += relu(h[n, c4*4..])
__global__ void pool_kernel(const float4* __restrict__ h, const int* __restrict__ batch,
                            float* __restrict__ pool, int comp, int N)
{
    int i = blockIdx.x * blockDim.x + threadIdx.x;
    if (i >= N * 45) return;
    int n = i / 45, c = i - n * 45;
    float4 v = h[i];
    v.x = fmaxf(v.x, 0.f); v.y = fmaxf(v.y, 0.f);
    v.z = fmaxf(v.z, 0.f); v.w = fmaxf(v.w, 0.f);
    float* p = pool + (size_t)batch[n] * FCD + comp * CCH + c * 4;
    asm volatile("red.global.add.v4.f32 [%0], {%1,%2,%3,%4};"
                 :: "l"(p), "f"(v.x), "f"(v.y), "f"(v.z), "f"(v.w) : "memory");
}

// mean + batchnorm (eval)
__global__ void bn_kernel(const float* __restrict__ pool, const float* __restrict__ cnt,
                          const float* __restrict__ gamma, const float* __restrict__ beta,
                          const float* __restrict__ mean, const float* __restrict__ var,
                          float* __restrict__ xout)
{
    int i = blockIdx.x * blockDim.x + threadIdx.x;
    if (i >= NGR * FCD) return;
    int b = i / FCD, j = i - b * FCD;
    int comp = j / CCH;
    float cn = fmaxf(cnt[comp * NGR + b], 1.f);
    float v = pool[i] / cn;
    v = (v - mean[j]) * rsqrtf(var[j] + 1e-5f) * gamma[j] + beta[j];
    xout[i] = v;
}

// ---------------- host orchestration ----------------
static inline void launch_gemm_nn(const float* A, const float* B, float* C,
                                  int N, int K, int M, cudaStream_t s)
{
    dim3 grid((N + 127) / 128, (M + 63) / 64);
    gemm_tf32<0, 0, 0><<<grid, 256, 0, s>>>(A, B, nullptr, C, N, K, M);
}
template<int RELU>
static inline void launch_gemm_nt_bias(const float* A, const float* B, const float* bias,
                                       float* C, int N, int K, int M, cudaStream_t s)
{
    dim3 grid((N + 127) / 128, (M + 63) / 64);
    gemm_tf32<1, RELU, 1><<<grid, 256, 0, s>>>(A, B, bias, C, N, K, M);
}

extern "C" void kernel_launch(void* const* d_in, const int* in_sizes, int n_in,
                              void* d_out, int out_size)
{
    cudaStream_t s = 0;

    const float* x[3]     = {(const float*)d_in[0], (const float*)d_in[3], (const float*)d_in[6]};
    const int*   ei[3]    = {(const int*)d_in[1], (const int*)d_in[4], (const int*)d_in[7]};
    const int*   batch[3] = {(const int*)d_in[2], (const int*)d_in[5], (const int*)d_in[8]};
    const float* convW = (const float*)d_in[9];
    const float* Wih   = (const float*)d_in[10];
    const float* Whh   = (const float*)d_in[11];
    const float* bih   = (const float*)d_in[12];
    const float* bhh   = (const float*)d_in[13];
    const float* bn_g  = (const float*)d_in[14];
    const float* bn_b  = (const float*)d_in[15];
    const float* bn_m  = (const float*)d_in[16];
    const float* bn_v  = (const float*)d_in[17];
    const float* fc1W  = (const float*)d_in[18];
    const float* fc1b  = (const float*)d_in[19];
    const float* fc2W  = (const float*)d_in[20];
    const float* fc2b  = (const float*)d_in[21];
    const float* fc25W = (const float*)d_in[22];
    const float* fc25b = (const float*)d_in[23];
    const float* fc3W  = (const float*)d_in[24];
    const float* fc3b  = (const float*)d_in[25];

    const int N = in_sizes[2];          // nodes per component (50000)
    const int E = in_sizes[1] / 2;      // edges (150000)
    const int F = in_sizes[0] / N;      // input feat dim (64)

    float *h_, *m_, *agg_, *gi_, *gh_, *pool_, *cnt_, *x_, *b1_, *b2_, *wtf_;
    cudaGetSymbolAddress((void**)&h_,   g_h);
    cudaGetSymbolAddress((void**)&m_,   g_m);
    cudaGetSymbolAddress((void**)&agg_, g_agg);
    cudaGetSymbolAddress((void**)&gi_,  g_gi);
    cudaGetSymbolAddress((void**)&gh_,  g_gh);
    cudaGetSymbolAddress((void**)&pool_,g_pool);
    cudaGetSymbolAddress((void**)&cnt_, g_cnt);
    cudaGetSymbolAddress((void**)&x_,   g_x);
    cudaGetSymbolAddress((void**)&b1_,  g_b1);
    cudaGetSymbolAddress((void**)&b2_,  g_b2);
    cudaGetSymbolAddress((void**)&wtf_, g_wtf);

    const int TPB = 256;
    const int nNC4 = N * 45;                 // N*CCH/4 float4 units
    const int gNC4 = (nNC4 + TPB - 1) / TPB;
    const int gScat = (E * 45 + TPB - 1) / TPB;

    // pre-convert all weights to tf32
    {
        struct { const float* src; int off; int n; } wl[7] = {
            {convW, OFF_CONV, 3 * LNUM * CCH * CCH},
            {Wih,   OFF_WIH,  3 * FCD * CCH},
            {Whh,   OFF_WHH,  3 * FCD * CCH},
            {fc1W,  OFF_FC1,  HID * FCD},
            {fc2W,  OFF_FC2,  HID * HID},
            {fc25W, OFF_FC25, FCD * HID},
            {fc3W,  OFF_FC3,  3 * FCD},
        };
        for (int i = 0; i < 7; i++)
            cvt_tf32_kernel<<<(wl[i].n + 511) / 512, 512, 0, s>>>(wl[i].src, wtf_ + wl[i].off, wl[i].n);
    }

    // clear pooled accumulators
    zero_kernel<<<(NGR * FCD / 4 + TPB - 1) / TPB, TPB, 0, s>>>((float4*)pool_, NGR * FCD / 4);
    zero_kernel<<<(3 * NGR / 4 + TPB - 1) / TPB, TPB, 0, s>>>((float4*)cnt_, 3 * NGR / 4);

    for (int comp = 0; comp < 3; comp++) {
        pad_kernel<<<gNC4, TPB, 0, s>>>((const float4*)x[comp], (float4*)h_, N, F / 4);
        const float* WihC = wtf_ + OFF_WIH + (size_t)comp * FCD * CCH;
        const float* WhhC = wtf_ + OFF_WHH + (size_t)comp * FCD * CCH;
        const float* bihC = bih + (size_t)comp * FCD;
        const float* bhhC = bhh + (size_t)comp * FCD;

        for (int l = 0; l < LNUM; l++) {
            const float* Wl = wtf_ + OFF_CONV + ((size_t)comp * LNUM + l) * CCH * CCH;
            // m = h @ Wl
            launch_gemm_nn(h_, Wl, m_, N, CCH, CCH, s);
            // agg = scatter_add(m[src] -> dst)
            zero_kernel<<<gNC4, TPB, 0, s>>>((float4*)agg_, nNC4);
            scatter_kernel<<<gScat, TPB, 0, s>>>(m_, ei[comp], agg_, E);
            // gi = agg @ Wih^T + bih ; gh = h @ Whh^T + bhh
            launch_gemm_nt_bias<0>(agg_, WihC, bihC, gi_, N, CCH, FCD, s);
            launch_gemm_nt_bias<0>(h_,  WhhC, bhhC, gh_, N, CCH, FCD, s);
            // GRU gate update (in place on h)
            gate_kernel<<<gNC4, TPB, 0, s>>>((const float4*)gi_, (const float4*)gh_, (float4*)h_, N);
        }
        count_kernel<<<(N + TPB - 1) / TPB, TPB, 0, s>>>(batch[comp], cnt_ + comp * NGR, N);
        pool_kernel<<<gNC4, TPB, 0, s>>>((const float4*)h_, batch[comp], pool_, comp, N);
    }

    // mean-pool + batchnorm
    bn_kernel<<<(NGR * FCD + TPB - 1) / TPB, TPB, 0, s>>>(pool_, cnt_, bn_g, bn_b, bn_m, bn_v, x_);

    // MLP head
    launch_gemm_nt_bias<1>(x_,  wtf_ + OFF_FC1,  fc1b,  b1_, NGR, FCD, HID, s);
    launch_gemm_nt_bias<1>(b1_, wtf_ + OFF_FC2,  fc2b,  b2_, NGR, HID, HID, s);
    launch_gemm_nt_bias<1>(b2_, wtf_ + OFF_FC25, fc25b, x_,  NGR, HID, FCD, s);
    launch_gemm_nt_bias<0>(x_,  wtf_ + OFF_FC3,  fc3b,  (float*)d_out, NGR, FCD, 3, s);
}

// round 4
// speedup vs baseline: 3.3164x; 1.0012x over previous
#include <cuda_runtime.h>
#include <cuda_bf16.h>
#include <math.h>
#include <stdint.h>

#define CCH 180
#define FCD 540           // 3*C
#define HID 1620          // 3*FC
#define NGR 2048
#define LNUM 6
#define MAXN 50000
#define MAXE 150000

// ---------------- scratch (device globals; no allocation allowed) ----------------
__device__ float g_h  [MAXN * CCH];
__device__ float g_m  [MAXN * CCH];
__device__ float g_agg[MAXN * CCH];
__device__ float g_gi [MAXN * FCD];
__device__ float g_gh [MAXN * FCD];
__device__ float g_pool[NGR * FCD];
__device__ float g_cnt [3 * NGR];
__device__ float g_x  [NGR * FCD];
__device__ float g_b1 [NGR * HID];
__device__ float g_b2 [NGR * HID];

// pre-converted (tf32-rounded) weights
#define OFF_CONV 0
#define OFF_WIH  972000
#define OFF_WHH  1263600
#define OFF_FC1  1555200
#define OFF_FC2  2430000
#define OFF_FC25 5054400
#define OFF_FC3  5929200
#define WTF_TOTAL 5930820
__device__ float g_wtf[WTF_TOTAL];

// ---------------- tf32 helpers ----------------
__device__ __forceinline__ uint32_t f2tf32(float f) {
    uint32_t u;
    asm("cvt.rna.tf32.f32 %0, %1;" : "=r"(u) : "f"(f));
    return u;
}

__device__ __forceinline__ void mma_tf32(float* c, const uint32_t* a, const uint32_t* b) {
    asm volatile(
        "mma.sync.aligned.m16n8k8.row.col.f32.tf32.tf32.f32 "
        "{%0,%1,%2,%3}, {%4,%5,%6,%7}, {%8,%9}, {%0,%1,%2,%3};"
        : "+f"(c[0]), "+f"(c[1]), "+f"(c[2]), "+f"(c[3])
        : "r"(a[0]), "r"(a[1]), "r"(a[2]), "r"(a[3]), "r"(b[0]), "r"(b[1]));
}

__device__ __forceinline__ void ldsm_x4(uint32_t& r0, uint32_t& r1, uint32_t& r2, uint32_t& r3,
                                        uint32_t saddr) {
    asm volatile("ldmatrix.sync.aligned.m8n8.x4.shared.b16 {%0,%1,%2,%3}, [%4];"
                 : "=r"(r0), "=r"(r1), "=r"(r2), "=r"(r3) : "r"(saddr));
}

__device__ __forceinline__ void cp_async16(uint32_t saddr, const void* gptr, int src_bytes) {
    asm volatile("cp.async.cg.shared.global [%0], [%1], 16, %2;"
                 :: "r"(saddr), "l"(gptr), "r"(src_bytes));
}
__device__ __forceinline__ void cp_commit() { asm volatile("cp.async.commit_group;"); }
__device__ __forceinline__ void cp_wait0()  { asm volatile("cp.async.wait_group 0;"); }

// ---------------- tf32 tensor-core GEMM v2 ----------------
// C[n,m] = sum_k A[n,k] * (TRANSB ? B[m,k] : B[k,m])  (+bias[m]) (+relu)
// A: f32 activations (converted to tf32 at smem store).
// B: pre-converted tf32 weights (raw copy).
// Block 128x64, k-tile 32, 8 warps (2 row x 4 col), warp 64x16.
// smem layouts [row][kchunk] with kchunk = 4 tf32 (16B), XOR swizzle kc^(row&7).
template<int TRANSB, int RELU, int BIAS>
__global__ __launch_bounds__(256)
void gemm_tf32(const float* __restrict__ A, const float* __restrict__ B,
               const float* __restrict__ bias, float* __restrict__ C,
               int N, int K, int M)
{
    __shared__ uint4 As4[2][128 * 8];   // 16KB / stage
    __shared__ uint4 Bs4[2][64 * 8];    // 8KB / stage

    const int tid  = threadIdx.x;
    const int lane = tid & 31;
    const int wid  = tid >> 5;
    const int wm   = (wid & 1) * 64;
    const int wn   = (wid >> 1) * 16;
    const int n0   = blockIdx.x * 128;
    const int m0   = blockIdx.y * 64;

    float acc[4][2][4];
    #pragma unroll
    for (int i = 0; i < 4; i++)
        #pragma unroll
        for (int j = 0; j < 2; j++)
            #pragma unroll
            for (int q = 0; q < 4; q++) acc[i][j][q] = 0.f;

    // ---- A loader: 128 rows x 8 chunks; thread -> row=tid>>1, chunks (tid&1)*4..+3
    const int arow = tid >> 1;
    const int ac0  = (tid & 1) * 4;
    const bool arow_ok = (n0 + arow) < N;
    const float* Ap = A + (size_t)(n0 + arow) * K;

    float4 pa[4];
    float4 pbnn[2];   // NN-path B staging regs

    auto loadA = [&](int k0) {
        #pragma unroll
        for (int c = 0; c < 4; c++) {
            int gk = k0 + (ac0 + c) * 4;
            pa[c] = make_float4(0.f, 0.f, 0.f, 0.f);
            if (arow_ok && gk < K)  // K % 4 == 0 -> full chunk valid
                pa[c] = *reinterpret_cast<const float4*>(Ap + gk);
        }
    };
    auto storeA = [&](int st) {
        #pragma unroll
        for (int c = 0; c < 4; c++) {
            int kc = ac0 + c;
            uint4 u;
            u.x = f2tf32(pa[c].x); u.y = f2tf32(pa[c].y);
            u.z = f2tf32(pa[c].z); u.w = f2tf32(pa[c].w);
            As4[st][(arow << 3) + (kc ^ (arow & 7))] = u;
        }
    };

    // ---- B loader
    auto issueB_nt = [&](int k0, int st) {   // B[m,k], raw tf32 copy via cp.async
        uint32_t sb = (uint32_t)__cvta_generic_to_shared(&Bs4[st][0]);
        #pragma unroll
        for (int i = 0; i < 2; i++) {
            int cid = tid * 2 + i;
            int m  = cid >> 3;
            int kc = cid & 7;
            int gm = m0 + m, gk = k0 + kc * 4;
            const float* gp = B + (size_t)gm * K + gk;
            int ok = (gm < M && gk < K) ? 16 : 0;
            cp_async16(sb + (((m << 3) + (kc ^ (m & 7))) << 4), gp, ok);
        }
    };
    auto loadB_nn = [&](int k0) {            // B[k,m] -> transpose via scalar LDG
        #pragma unroll
        for (int i = 0; i < 2; i++) {
            int s = tid + i * 256;           // s = kc*64 + m
            int kc = s >> 6, m = s & 63;
            int gm = m0 + m;
            float* d = &pbnn[i].x;
            #pragma unroll
            for (int q = 0; q < 4; q++) {
                int gk = k0 + kc * 4 + q;
                d[q] = (gm < M && gk < K) ? B[(size_t)gk * M + gm] : 0.f;
            }
        }
    };
    auto storeB_nn = [&](int st) {
        #pragma unroll
        for (int i = 0; i < 2; i++) {
            int s = tid + i * 256;
            int kc = s >> 6, m = s & 63;
            uint4 u;
            u.x = __float_as_uint(pbnn[i].x); u.y = __float_as_uint(pbnn[i].y);
            u.z = __float_as_uint(pbnn[i].z); u.w = __float_as_uint(pbnn[i].w);
            Bs4[st][(m << 3) + (kc ^ (m & 7))] = u;
        }
    };

    const int g  = lane >> 3;
    const int l7 = lane & 7;

    auto compute = [&](int st) {
        uint32_t aBase = (uint32_t)__cvta_generic_to_shared(&As4[st][0]);
        uint32_t bBase = (uint32_t)__cvta_generic_to_shared(&Bs4[st][0]);
        #pragma unroll
        for (int kb = 0; kb < 32; kb += 8) {
            const int kq = kb >> 2;
            uint32_t a[4][4];
            #pragma unroll
            for (int i = 0; i < 4; i++) {
                int row = wm + i * 16 + ((g & 1) << 3) + l7;
                int kc  = kq + (g >> 1);
                uint32_t ad = aBase + (((row << 3) + (kc ^ (row & 7))) << 4);
                ldsm_x4(a[i][0], a[i][1], a[i][2], a[i][3], ad);
            }
            uint32_t b[4];
            {
                int nrow = wn + ((g >> 1) << 3) + l7;
                int kc   = kq + (g & 1);
                uint32_t bd = bBase + (((nrow << 3) + (kc ^ (nrow & 7))) << 4);
                ldsm_x4(b[0], b[1], b[2], b[3], bd);
            }
            #pragma unroll
            for (int i = 0; i < 4; i++) {
                mma_tf32(acc[i][0], a[i], &b[0]);
                mma_tf32(acc[i][1], a[i], &b[2]);
            }
        }
    };

    const int T = (K + 31) / 32;

    // prologue: fill stage 0
    loadA(0);
    if (TRANSB) issueB_nt(0, 0); else loadB_nn(0);
    storeA(0);
    if (!TRANSB) storeB_nn(0);
    if (TRANSB) { cp_commit(); cp_wait0(); }
    __syncthreads();

    for (int kt = 0; kt < T; kt++) {
        const int cur = kt & 1, nxt = cur ^ 1;
        const bool more = (kt + 1) < T;
        if (more) {
            loadA((kt + 1) * 32);
            if (TRANSB) { issueB_nt((kt + 1) * 32, nxt); cp_commit(); }
            else loadB_nn((kt + 1) * 32);
        }
        compute(cur);
        if (more) {
            storeA(nxt);
            if (!TRANSB) storeB_nn(nxt);
            if (TRANSB) cp_wait0();
            __syncthreads();
        }
    }

    // epilogue
    #pragma unroll
    for (int i = 0; i < 4; i++) {
        #pragma unroll
        for (int j = 0; j < 2; j++) {
            int r0 = n0 + wm + i * 16 + (lane >> 2);
            int c0 = m0 + wn + j * 8 + (lane & 3) * 2;
            if (c0 >= M) continue;
            bool c1ok = (c0 + 1) < M;
            float bv0 = BIAS ? bias[c0] : 0.f;
            float bv1 = (BIAS && c1ok) ? bias[c0 + 1] : 0.f;
            #pragma unroll
            for (int hrow = 0; hrow < 2; hrow++) {
                int r = r0 + hrow * 8;
                if (r >= N) continue;
                float v0 = acc[i][j][hrow * 2 + 0] + bv0;
                float v1 = acc[i][j][hrow * 2 + 1] + bv1;
                if (RELU) { v0 = fmaxf(v0, 0.f); v1 = fmaxf(v1, 0.f); }
                if (c1ok && ((M & 1) == 0)) {
                    *reinterpret_cast<float2*>(C + (size_t)r * M + c0) = make_float2(v0, v1);
                } else {
                    C[(size_t)r * M + c0] = v0;
                    if (c1ok) C[(size_t)r * M + c0 + 1] = v1;
                }
            }
        }
    }
}

// ---------------- weight pre-conversion ----------------
__global__ void cvt_tf32_kernel(const float* __restrict__ in, float* __restrict__ out, int n)
{
    int i = blockIdx.x * blockDim.x + threadIdx.x;
    if (i < n) out[i] = __uint_as_float(f2tf32(in[i]));
}

// ---------------- elementwise / graph kernels ----------------
__global__ void pad_kernel(const float4* __restrict__ x, float4* __restrict__ h, int N, int F4)
{
    int i = blockIdx.x * blockDim.x + threadIdx.x;
    if (i >= N * 45) return;
    int n = i / 45, c = i - n * 45;
    float4 v = make_float4(0.f, 0.f, 0.f, 0.f);
    if (c < F4) v = x[(size_t)n * F4 + c];
    h[i] = v;
}

__global__ void zero_kernel(float4* __restrict__ p, int n4)
{
    int i = blockIdx.x * blockDim.x + threadIdx.x;
    if (i < n4) p[i] = make_float4(0.f, 0.f, 0.f, 0.f);
}

// agg[dst] += m[src], 45 float4 chunks per edge, vectorized reduction (no return)
__global__ void scatter_kernel(const float* __restrict__ msg, const int* __restrict__ ei,
                               float* __restrict__ agg, int E)
{
    int i = blockIdx.x * blockDim.x + threadIdx.x;
    if (i >= E * 45) return;
    int e = i / 45, c = i - e * 45;
    int src = ei[e];
    int dst = ei[E + e];
    float4 v = reinterpret_cast<const float4*>(msg + (size_t)src * CCH)[c];
    float* p = agg + (size_t)dst * CCH + c * 4;
    asm volatile("red.global.add.v4.f32 [%0], {%1,%2,%3,%4};"
                 :: "l"(p), "f"(v.x), "f"(v.y), "f"(v.z), "f"(v.w) : "memory");
}

__device__ __forceinline__ float sigm(float x) { return 1.f / (1.f + __expf(-x)); }

__global__ void gate_kernel(const float4* __restrict__ gi, const float4* __restrict__ gh,
                            float4* __restrict__ h, int N)
{
    int i = blockIdx.x * blockDim.x + threadIdx.x;
    if (i >= N * 45) return;
    int n = i / 45, c = i - n * 45;
    const float4* pi = gi + (size_t)n * 135;
    const float4* ph = gh + (size_t)n * 135;
    float4 ir = pi[c], iz = pi[c + 45], in4 = pi[c + 90];
    float4 hr = ph[c], hz = ph[c + 45], hn = ph[c + 90];
    float4 ho = h[i];
    float4 o;
    {
        float r = sigm(ir.x + hr.x), z = sigm(iz.x + hz.x);
        float nn = tanhf(in4.x + r * hn.x);
        o.x = (1.f - z) * nn + z * ho.x;
    }
    {
        float r = sigm(ir.y + hr.y), z = sigm(iz.y + hz.y);
        float nn = tanhf(in4.y + r * hn.y);
        o.y = (1.f - z) * nn + z * ho.y;
    }
    {
        float r = sigm(ir.z + hr.z), z = sigm(iz.z + hz.z);
        float nn = tanhf(in4.z + r * hn.z);
        o.z = (1.f - z) * nn + z * ho.z;
    }
    {
        float r = sigm(ir.w + hr.w), z = sigm(iz.w + hz.w);
        float nn = tanhf(in4.w + r * hn.w);
        o.w = (1.f - z) * nn + z * ho.w;
    }
    h[i] = o;
}

__global__ void count_kernel(const int* __restrict__ batch, float* __restrict__ cnt, int N)
{
    int i = blockIdx.x * blockDim.x + threadIdx.x;
    if (i < N) atomicAdd(&cnt[batch[i]], 1.f);
}

// pooled[b, comp*180 + c4*4..] += relu(h[n, c4*4..])
__global__ void pool_kernel(const float4* __restrict__ h, const int* __restrict__ batch,
                            float* __restrict__ pool, int comp, int N)
{
    int i = blockIdx.x * blockDim.x + threadIdx.x;
    if (i >= N * 45) return;
    int n = i / 45, c = i - n * 45;
    float4 v = h[i];
    v.x = fmaxf(v.x, 0.f); v.y = fmaxf(v.y, 0.f);
    v.z = fmaxf(v.z, 0.f); v.w = fmaxf(v.w, 0.f);
    float* p = pool + (size_t)batch[n] * FCD + comp * CCH + c * 4;
    asm volatile("red.global.add.v4.f32 [%0], {%1,%2,%3,%4};"
                 :: "l"(p), "f"(v.x), "f"(v.y), "f"(v.z), "f"(v.w) : "memory");
}

// mean + batchnorm (eval)
__global__ void bn_kernel(const float* __restrict__ pool, const float* __restrict__ cnt,
                          const float* __restrict__ gamma, const float* __restrict__ beta,
                          const float* __restrict__ mean, const float* __restrict__ var,
                          float* __restrict__ xout)
{
    int i = blockIdx.x * blockDim.x + threadIdx.x;
    if (i >= NGR * FCD) return;
    int b = i / FCD, j = i - b * FCD;
    int comp = j / CCH;
    float cn = fmaxf(cnt[comp * NGR + b], 1.f);
    float v = pool[i] / cn;
    v = (v - mean[j]) * rsqrtf(var[j] + 1e-5f) * gamma[j] + beta[j];
    xout[i] = v;
}

// ---------------- host orchestration ----------------
static inline void launch_gemm_nn(const float* A, const float* B, float* C,
                                  int N, int K, int M, cudaStream_t s)
{
    dim3 grid((N + 127) / 128, (M + 63) / 64);
    gemm_tf32<0, 0, 0><<<grid, 256, 0, s>>>(A, B, nullptr, C, N, K, M);
}
template<int RELU>
static inline void launch_gemm_nt_bias(const float* A, const float* B, const float* bias,
                                       float* C, int N, int K, int M, cudaStream_t s)
{
    dim3 grid((N + 127) / 128, (M + 63) / 64);
    gemm_tf32<1, RELU, 1><<<grid, 256, 0, s>>>(A, B, bias, C, N, K, M);
}

extern "C" void kernel_launch(void* const* d_in, const int* in_sizes, int n_in,
                              void* d_out, int out_size)
{
    cudaStream_t s = 0;

    const float* x[3]     = {(const float*)d_in[0], (const float*)d_in[3], (const float*)d_in[6]};
    const int*   ei[3]    = {(const int*)d_in[1], (const int*)d_in[4], (const int*)d_in[7]};
    const int*   batch[3] = {(const int*)d_in[2], (const int*)d_in[5], (const int*)d_in[8]};
    const float* convW = (const float*)d_in[9];
    const float* Wih   = (const float*)d_in[10];
    const float* Whh   = (const float*)d_in[11];
    const float* bih   = (const float*)d_in[12];
    const float* bhh   = (const float*)d_in[13];
    const float* bn_g  = (const float*)d_in[14];
    const float* bn_b  = (const float*)d_in[15];
    const float* bn_m  = (const float*)d_in[16];
    const float* bn_v  = (const float*)d_in[17];
    const float* fc1W  = (const float*)d_in[18];
    const float* fc1b  = (const float*)d_in[19];
    const float* fc2W  = (const float*)d_in[20];
    const float* fc2b  = (const float*)d_in[21];
    const float* fc25W = (const float*)d_in[22];
    const float* fc25b = (const float*)d_in[23];
    const float* fc3W  = (const float*)d_in[24];
    const float* fc3b  = (const float*)d_in[25];

    const int N = in_sizes[2];          // nodes per component (50000)
    const int E = in_sizes[1] / 2;      // edges (150000)
    const int F = in_sizes[0] / N;      // input feat dim (64)

    float *h_, *m_, *agg_, *gi_, *gh_, *pool_, *cnt_, *x_, *b1_, *b2_, *wtf_;
    cudaGetSymbolAddress((void**)&h_,   g_h);
    cudaGetSymbolAddress((void**)&m_,   g_m);
    cudaGetSymbolAddress((void**)&agg_, g_agg);
    cudaGetSymbolAddress((void**)&gi_,  g_gi);
    cudaGetSymbolAddress((void**)&gh_,  g_gh);
    cudaGetSymbolAddress((void**)&pool_,g_pool);
    cudaGetSymbolAddress((void**)&cnt_, g_cnt);
    cudaGetSymbolAddress((void**)&x_,   g_x);
    cudaGetSymbolAddress((void**)&b1_,  g_b1);
    cudaGetSymbolAddress((void**)&b2_,  g_b2);
    cudaGetSymbolAddress((void**)&wtf_, g_wtf);

    const int TPB = 256;
    const int nNC4 = N * 45;                 // N*CCH/4 float4 units
    const int gNC4 = (nNC4 + TPB - 1) / TPB;
    const int gScat = (E * 45 + TPB - 1) / TPB;

    // pre-convert all weights to tf32
    {
        struct { const float* src; int off; int n; } wl[7] = {
            {convW, OFF_CONV, 3 * LNUM * CCH * CCH},
            {Wih,   OFF_WIH,  3 * FCD * CCH},
            {Whh,   OFF_WHH,  3 * FCD * CCH},
            {fc1W,  OFF_FC1,  HID * FCD},
            {fc2W,  OFF_FC2,  HID * HID},
            {fc25W, OFF_FC25, FCD * HID},
            {fc3W,  OFF_FC3,  3 * FCD},
        };
        for (int i = 0; i < 7; i++)
            cvt_tf32_kernel<<<(wl[i].n + 511) / 512, 512, 0, s>>>(wl[i].src, wtf_ + wl[i].off, wl[i].n);
    }

    // clear pooled accumulators
    zero_kernel<<<(NGR * FCD / 4 + TPB - 1) / TPB, TPB, 0, s>>>((float4*)pool_, NGR * FCD / 4);
    zero_kernel<<<(3 * NGR / 4 + TPB - 1) / TPB, TPB, 0, s>>>((float4*)cnt_, 3 * NGR / 4);

    for (int comp = 0; comp < 3; comp++) {
        pad_kernel<<<gNC4, TPB, 0, s>>>((const float4*)x[comp], (float4*)h_, N, F / 4);
        const float* WihC = wtf_ + OFF_WIH + (size_t)comp * FCD * CCH;
        const float* WhhC = wtf_ + OFF_WHH + (size_t)comp * FCD * CCH;
        const float* bihC = bih + (size_t)comp * FCD;
        const float* bhhC = bhh + (size_t)comp * FCD;

        for (int l = 0; l < LNUM; l++) {
            const float* Wl = wtf_ + OFF_CONV + ((size_t)comp * LNUM + l) * CCH * CCH;
            // m = h @ Wl
            launch_gemm_nn(h_, Wl, m_, N, CCH, CCH, s);
            // agg = scatter_add(m[src] -> dst)
            zero_kernel<<<gNC4, TPB, 0, s>>>((float4*)agg_, nNC4);
            scatter_kernel<<<gScat, TPB, 0, s>>>(m_, ei[comp], agg_, E);
            // gi = agg @ Wih^T + bih ; gh = h @ Whh^T + bhh
            launch_gemm_nt_bias<0>(agg_, WihC, bihC, gi_, N, CCH, FCD, s);
            launch_gemm_nt_bias<0>(h_,  WhhC, bhhC, gh_, N, CCH, FCD, s);
            // GRU gate update (in place on h)
            gate_kernel<<<gNC4, TPB, 0, s>>>((const float4*)gi_, (const float4*)gh_, (float4*)h_, N);
        }
        count_kernel<<<(N + TPB - 1) / TPB, TPB, 0, s>>>(batch[comp], cnt_ + comp * NGR, N);
        pool_kernel<<<gNC4, TPB, 0, s>>>((const float4*)h_, batch[comp], pool_, comp, N);
    }

    // mean-pool + batchnorm
    bn_kernel<<<(NGR * FCD + TPB - 1) / TPB, TPB, 0, s>>>(pool_, cnt_, bn_g, bn_b, bn_m, bn_v, x_);

    // MLP head
    launch_gemm_nt_bias<1>(x_,  wtf_ + OFF_FC1,  fc1b,  b1_, NGR, FCD, HID, s);
    launch_gemm_nt_bias<1>(b1_, wtf_ + OFF_FC2,  fc2b,  b2_, NGR, HID, HID, s);
    launch_gemm_nt_bias<1>(b2_, wtf_ + OFF_FC25, fc25b, x_,  NGR, HID, FCD, s);
    launch_gemm_nt_bias<0>(x_,  wtf_ + OFF_FC3,  fc3b,  (float*)d_out, NGR, FCD, 3, s);
}

// round 5
// speedup vs baseline: 3.8140x; 1.1500x over previous
#include <cuda_runtime.h>
#include <cuda_bf16.h>
#include <math.h>
#include <stdint.h>

#define CCH 180
#define FCD 540           // 3*C
#define HID 1620          // 3*FC
#define NGR 2048
#define LNUM 6
#define MAXN 50000
#define MAXE 150000

// ---------------- scratch (device globals; no allocation allowed) ----------------
__device__ float g_h  [MAXN * CCH];
__device__ float g_hn [MAXN * CCH];
__device__ float g_m  [MAXN * CCH];
__device__ float g_agg[MAXN * CCH];
__device__ float g_pool[NGR * FCD];
__device__ float g_cnt [3 * NGR];
__device__ float g_x  [NGR * FCD];
__device__ float g_b1 [NGR * HID];
__device__ float g_b2 [NGR * HID];

// pre-converted (tf32-rounded) weights
#define OFF_CONV 0
#define OFF_WIH  972000
#define OFF_WHH  1263600
#define OFF_FC1  1555200
#define OFF_FC2  2430000
#define OFF_FC25 5054400
#define OFF_FC3  5929200
#define WTF_TOTAL 5930820
__device__ float g_wtf[WTF_TOTAL];

// ---------------- tf32 helpers ----------------
__device__ __forceinline__ uint32_t f2tf32(float f) {
    uint32_t u;
    asm("cvt.rna.tf32.f32 %0, %1;" : "=r"(u) : "f"(f));
    return u;
}

__device__ __forceinline__ void mma_tf32(float* c, const uint32_t* a, const uint32_t* b) {
    asm volatile(
        "mma.sync.aligned.m16n8k8.row.col.f32.tf32.tf32.f32 "
        "{%0,%1,%2,%3}, {%4,%5,%6,%7}, {%8,%9}, {%0,%1,%2,%3};"
        : "+f"(c[0]), "+f"(c[1]), "+f"(c[2]), "+f"(c[3])
        : "r"(a[0]), "r"(a[1]), "r"(a[2]), "r"(a[3]), "r"(b[0]), "r"(b[1]));
}

__device__ __forceinline__ void ldsm_x4(uint32_t& r0, uint32_t& r1, uint32_t& r2, uint32_t& r3,
                                        uint32_t saddr) {
    asm volatile("ldmatrix.sync.aligned.m8n8.x4.shared.b16 {%0,%1,%2,%3}, [%4];"
                 : "=r"(r0), "=r"(r1), "=r"(r2), "=r"(r3) : "r"(saddr));
}

__device__ __forceinline__ void cp_async16(uint32_t saddr, const void* gptr, int src_bytes) {
    asm volatile("cp.async.cg.shared.global [%0], [%1], 16, %2;"
                 :: "r"(saddr), "l"(gptr), "r"(src_bytes));
}
__device__ __forceinline__ void cp_commit() { asm volatile("cp.async.commit_group;"); }
__device__ __forceinline__ void cp_wait0()  { asm volatile("cp.async.wait_group 0;"); }

__device__ __forceinline__ float sigm(float x) { return 1.f / (1.f + __expf(-x)); }

// ---------------- generic tf32 tensor-core GEMM (NN conv-step + MLP head) ----------------
// C[n,m] = sum_k A[n,k(lda)] * (TRANSB ? B[m,k] : B[k,m])  (+bias[m]) (+relu)
template<int TRANSB, int RELU, int BIAS>
__global__ __launch_bounds__(256)
void gemm_tf32(const float* __restrict__ A, const float* __restrict__ B,
               const float* __restrict__ bias, float* __restrict__ C,
               int N, int K, int M, int lda)
{
    __shared__ uint4 As4[2][128 * 8];   // 16KB / stage
    __shared__ uint4 Bs4[2][64 * 8];    // 8KB / stage

    const int tid  = threadIdx.x;
    const int lane = tid & 31;
    const int wid  = tid >> 5;
    const int wm   = (wid & 1) * 64;
    const int wn   = (wid >> 1) * 16;
    const int n0   = blockIdx.x * 128;
    const int m0   = blockIdx.y * 64;

    float acc[4][2][4];
    #pragma unroll
    for (int i = 0; i < 4; i++)
        #pragma unroll
        for (int j = 0; j < 2; j++)
            #pragma unroll
            for (int q = 0; q < 4; q++) acc[i][j][q] = 0.f;

    const int arow = tid >> 1;
    const int ac0  = (tid & 1) * 4;
    const bool arow_ok = (n0 + arow) < N;
    const float* Ap = A + (size_t)(n0 + arow) * lda;

    float4 pa[4];
    float4 pbnn[2];

    auto loadA = [&](int k0) {
        #pragma unroll
        for (int c = 0; c < 4; c++) {
            int gk = k0 + (ac0 + c) * 4;
            pa[c] = make_float4(0.f, 0.f, 0.f, 0.f);
            if (arow_ok && gk < K)  // K % 4 == 0
                pa[c] = *reinterpret_cast<const float4*>(Ap + gk);
        }
    };
    auto storeA = [&](int st) {
        #pragma unroll
        for (int c = 0; c < 4; c++) {
            int kc = ac0 + c;
            uint4 u;
            u.x = f2tf32(pa[c].x); u.y = f2tf32(pa[c].y);
            u.z = f2tf32(pa[c].z); u.w = f2tf32(pa[c].w);
            As4[st][(arow << 3) + (kc ^ (arow & 7))] = u;
        }
    };

    auto issueB_nt = [&](int k0, int st) {
        uint32_t sb = (uint32_t)__cvta_generic_to_shared(&Bs4[st][0]);
        #pragma unroll
        for (int i = 0; i < 2; i++) {
            int cid = tid * 2 + i;
            int m  = cid >> 3;
            int kc = cid & 7;
            int gm = m0 + m, gk = k0 + kc * 4;
            const float* gp = B + (size_t)gm * K + gk;
            int ok = (gm < M && gk < K) ? 16 : 0;
            cp_async16(sb + (((m << 3) + (kc ^ (m & 7))) << 4), gp, ok);
        }
    };
    auto loadB_nn = [&](int k0) {
        #pragma unroll
        for (int i = 0; i < 2; i++) {
            int s = tid + i * 256;
            int kc = s >> 6, m = s & 63;
            int gm = m0 + m;
            float* d = &pbnn[i].x;
            #pragma unroll
            for (int q = 0; q < 4; q++) {
                int gk = k0 + kc * 4 + q;
                d[q] = (gm < M && gk < K) ? B[(size_t)gk * M + gm] : 0.f;
            }
        }
    };
    auto storeB_nn = [&](int st) {
        #pragma unroll
        for (int i = 0; i < 2; i++) {
            int s = tid + i * 256;
            int kc = s >> 6, m = s & 63;
            uint4 u;
            u.x = __float_as_uint(pbnn[i].x); u.y = __float_as_uint(pbnn[i].y);
            u.z = __float_as_uint(pbnn[i].z); u.w = __float_as_uint(pbnn[i].w);
            Bs4[st][(m << 3) + (kc ^ (m & 7))] = u;
        }
    };

    const int g  = lane >> 3;
    const int l7 = lane & 7;

    auto compute = [&](int st) {
        uint32_t aBase = (uint32_t)__cvta_generic_to_shared(&As4[st][0]);
        uint32_t bBase = (uint32_t)__cvta_generic_to_shared(&Bs4[st][0]);
        #pragma unroll
        for (int kb = 0; kb < 32; kb += 8) {
            const int kq = kb >> 2;
            uint32_t a[4][4];
            #pragma unroll
            for (int i = 0; i < 4; i++) {
                int row = wm + i * 16 + ((g & 1) << 3) + l7;
                int kc  = kq + (g >> 1);
                uint32_t ad = aBase + (((row << 3) + (kc ^ (row & 7))) << 4);
                ldsm_x4(a[i][0], a[i][1], a[i][2], a[i][3], ad);
            }
            uint32_t b[4];
            {
                int nrow = wn + ((g >> 1) << 3) + l7;
                int kc   = kq + (g & 1);
                uint32_t bd = bBase + (((nrow << 3) + (kc ^ (nrow & 7))) << 4);
                ldsm_x4(b[0], b[1], b[2], b[3], bd);
            }
            #pragma unroll
            for (int i = 0; i < 4; i++) {
                mma_tf32(acc[i][0], a[i], &b[0]);
                mma_tf32(acc[i][1], a[i], &b[2]);
            }
        }
    };

    const int T = (K + 31) / 32;

    loadA(0);
    if (TRANSB) issueB_nt(0, 0); else loadB_nn(0);
    storeA(0);
    if (!TRANSB) storeB_nn(0);
    if (TRANSB) { cp_commit(); cp_wait0(); }
    __syncthreads();

    for (int kt = 0; kt < T; kt++) {
        const int cur = kt & 1, nxt = cur ^ 1;
        const bool more = (kt + 1) < T;
        if (more) {
            loadA((kt + 1) * 32);
            if (TRANSB) { issueB_nt((kt + 1) * 32, nxt); cp_commit(); }
            else loadB_nn((kt + 1) * 32);
        }
        compute(cur);
        if (more) {
            storeA(nxt);
            if (!TRANSB) storeB_nn(nxt);
            if (TRANSB) cp_wait0();
            __syncthreads();
        }
    }

    #pragma unroll
    for (int i = 0; i < 4; i++) {
        #pragma unroll
        for (int j = 0; j < 2; j++) {
            int r0 = n0 + wm + i * 16 + (lane >> 2);
            int c0 = m0 + wn + j * 8 + (lane & 3) * 2;
            if (c0 >= M) continue;
            bool c1ok = (c0 + 1) < M;
            float bv0 = BIAS ? bias[c0] : 0.f;
            float bv1 = (BIAS && c1ok) ? bias[c0 + 1] : 0.f;
            #pragma unroll
            for (int hrow = 0; hrow < 2; hrow++) {
                int r = r0 + hrow * 8;
                if (r >= N) continue;
                float v0 = acc[i][j][hrow * 2 + 0] + bv0;
                float v1 = acc[i][j][hrow * 2 + 1] + bv1;
                if (RELU) { v0 = fmaxf(v0, 0.f); v1 = fmaxf(v1, 0.f); }
                if (c1ok && ((M & 1) == 0)) {
                    *reinterpret_cast<float2*>(C + (size_t)r * M + c0) = make_float2(v0, v1);
                } else {
                    C[(size_t)r * M + c0] = v0;
                    if (c1ok) C[(size_t)r * M + c0 + 1] = v1;
                }
            }
        }
    }
}

// ---------------- fused GRU kernel ----------------
// Computes, for a 64-row x 64-gate-col tile (grid.y over 3 col-blocks of 180):
//   gi_g = agg @ Wih_g^T + bih_g,  gh_g = h @ Whh_g^T + bhh_g   (g = r,z,n)
// then h_new = (1-z)*tanh(in + r*hn) + z*h_old, written directly.
// 6 simultaneous MMA accumulator sets; 2-stage cp.async pipeline, k-tile 32.
// Dynamic smem: 2 stages x 8 tiles (Aagg, Ah, B0..B5) x 512 uint4 = 128KB.
__global__ __launch_bounds__(256, 1)
void gru_fused(const float* __restrict__ Aagg, const float* __restrict__ Ah,
               const float* __restrict__ Wih, const float* __restrict__ Whh,
               const float* __restrict__ bih, const float* __restrict__ bhh,
               float* __restrict__ hnew, int N)
{
    extern __shared__ uint4 sm[];
    const int tid  = threadIdx.x;
    const int lane = tid & 31;
    const int wid  = tid >> 5;
    const int wm   = (wid & 1) * 32;
    const int wn   = (wid >> 1) * 16;
    const int n0   = blockIdx.x * 64;
    const int m0   = blockIdx.y * 64;

    float acc_i[3][2][2][4];
    float acc_h[3][2][2][4];
    #pragma unroll
    for (int gi = 0; gi < 3; gi++)
        #pragma unroll
        for (int i = 0; i < 2; i++)
            #pragma unroll
            for (int j = 0; j < 2; j++)
                #pragma unroll
                for (int q = 0; q < 4; q++) { acc_i[gi][i][j][q] = 0.f; acc_h[gi][i][j][q] = 0.f; }

    const int arow = tid >> 2;          // 0..63
    const int ac0  = (tid & 3) * 2;     // chunk base
    const bool arow_ok = (n0 + arow) < N;
    const float* Aggp = Aagg + (size_t)(n0 + arow) * CCH;
    const float* Ahp  = Ah   + (size_t)(n0 + arow) * CCH;

    float4 pagg[2], ph[2];

    auto loadA = [&](int k0) {
        #pragma unroll
        for (int c = 0; c < 2; c++) {
            int gk = k0 + (ac0 + c) * 4;
            pagg[c] = make_float4(0.f, 0.f, 0.f, 0.f);
            ph[c]   = make_float4(0.f, 0.f, 0.f, 0.f);
            if (arow_ok && gk < CCH) {  // CCH % 4 == 0
                pagg[c] = *reinterpret_cast<const float4*>(Aggp + gk);
                ph[c]   = *reinterpret_cast<const float4*>(Ahp + gk);
            }
        }
    };
    auto storeA = [&](int st) {
        uint4* Sa = sm + st * 4096;
        uint4* Sh = Sa + 512;
        #pragma unroll
        for (int c = 0; c < 2; c++) {
            int kc = ac0 + c;
            int idx = (arow << 3) + (kc ^ (arow & 7));
            uint4 u;
            u.x = f2tf32(pagg[c].x); u.y = f2tf32(pagg[c].y);
            u.z = f2tf32(pagg[c].z); u.w = f2tf32(pagg[c].w);
            Sa[idx] = u;
            u.x = f2tf32(ph[c].x); u.y = f2tf32(ph[c].y);
            u.z = f2tf32(ph[c].z); u.w = f2tf32(ph[c].w);
            Sh[idx] = u;
        }
    };
    auto issueB = [&](int k0, int st) {
        uint32_t sb = (uint32_t)__cvta_generic_to_shared(sm + st * 4096 + 1024);
        #pragma unroll
        for (int mat = 0; mat < 6; mat++) {
            const float* W = (mat < 3) ? Wih : Whh;
            int goff = (mat % 3) * CCH;
            #pragma unroll
            for (int j = 0; j < 2; j++) {
                int cid = tid * 2 + j;         // 0..511
                int row = cid >> 3, kc = cid & 7;
                int gm = m0 + row;
                int gk = k0 + kc * 4;
                const float* gp = W + (size_t)(goff + gm) * CCH + gk;
                int ok = (gm < CCH && gk < CCH) ? 16 : 0;
                cp_async16(sb + ((mat * 512 + (row << 3) + (kc ^ (row & 7))) << 4), gp, ok);
            }
        }
    };

    const int g  = lane >> 3;
    const int l7 = lane & 7;

    auto compute = [&](int st) {
        uint32_t aBase = (uint32_t)__cvta_generic_to_shared(sm + st * 4096);
        uint32_t hBase = aBase + 512 * 16;
        uint32_t bBase = aBase + 1024 * 16;
        #pragma unroll
        for (int kb = 0; kb < 32; kb += 8) {
            const int kq = kb >> 2;
            uint32_t ag[2][4], ah[2][4];
            #pragma unroll
            for (int i = 0; i < 2; i++) {
                int row = wm + i * 16 + ((g & 1) << 3) + l7;
                int kc  = kq + (g >> 1);
                uint32_t off = ((row << 3) + (kc ^ (row & 7))) << 4;
                ldsm_x4(ag[i][0], ag[i][1], ag[i][2], ag[i][3], aBase + off);
                ldsm_x4(ah[i][0], ah[i][1], ah[i][2], ah[i][3], hBase + off);
            }
            uint32_t b[6][4];
            {
                int nrow = wn + ((g >> 1) << 3) + l7;
                int kc   = kq + (g & 1);
                uint32_t off = ((nrow << 3) + (kc ^ (nrow & 7))) << 4;
                #pragma unroll
                for (int mat = 0; mat < 6; mat++)
                    ldsm_x4(b[mat][0], b[mat][1], b[mat][2], b[mat][3],
                            bBase + (mat * 512 << 4) + off);
            }
            #pragma unroll
            for (int gi = 0; gi < 3; gi++)
                #pragma unroll
                for (int i = 0; i < 2; i++) {
                    mma_tf32(acc_i[gi][i][0], ag[i], &b[gi][0]);
                    mma_tf32(acc_i[gi][i][1], ag[i], &b[gi][2]);
                    mma_tf32(acc_h[gi][i][0], ah[i], &b[3 + gi][0]);
                    mma_tf32(acc_h[gi][i][1], ah[i], &b[3 + gi][2]);
                }
        }
    };

    const int T = (CCH + 31) / 32;   // 6

    loadA(0); issueB(0, 0);
    storeA(0);
    cp_commit(); cp_wait0();
    __syncthreads();

    for (int kt = 0; kt < T; kt++) {
        const int cur = kt & 1, nxt = cur ^ 1;
        const bool more = (kt + 1) < T;
        if (more) {
            loadA((kt + 1) * 32);
            issueB((kt + 1) * 32, nxt);
            cp_commit();
        }
        compute(cur);
        if (more) {
            storeA(nxt);
            cp_wait0();
            __syncthreads();
        }
    }

    // gate epilogue
    #pragma unroll
    for (int i = 0; i < 2; i++) {
        #pragma unroll
        for (int j = 0; j < 2; j++) {
            int rbase = n0 + wm + i * 16 + (lane >> 2);
            int c0 = m0 + wn + j * 8 + (lane & 3) * 2;
            #pragma unroll
            for (int q = 0; q < 2; q++) {          // row half
                int r = rbase + q * 8;
                if (r >= N) continue;
                #pragma unroll
                for (int p = 0; p < 2; p++) {      // col pair
                    int c = c0 + p;
                    if (c >= CCH) continue;
                    int v = q * 2 + p;
                    float ir = acc_i[0][i][j][v] + bih[c];
                    float iz = acc_i[1][i][j][v] + bih[c + CCH];
                    float in = acc_i[2][i][j][v] + bih[c + 2 * CCH];
                    float hr = acc_h[0][i][j][v] + bhh[c];
                    float hz = acc_h[1][i][j][v] + bhh[c + CCH];
                    float hn = acc_h[2][i][j][v] + bhh[c + 2 * CCH];
                    float rg = sigm(ir + hr);
                    float z  = sigm(iz + hz);
                    float nn = tanhf(in + rg * hn);
                    float ho = Ah[(size_t)r * CCH + c];
                    hnew[(size_t)r * CCH + c] = (1.f - z) * nn + z * ho;
                }
            }
        }
    }
}

// ---------------- weight pre-conversion ----------------
__global__ void cvt_tf32_kernel(const float* __restrict__ in, float* __restrict__ out, int n)
{
    int i = blockIdx.x * blockDim.x + threadIdx.x;
    if (i < n) out[i] = __uint_as_float(f2tf32(in[i]));
}

// ---------------- elementwise / graph kernels ----------------
__global__ void pad_kernel(const float4* __restrict__ x, float4* __restrict__ h, int N, int F4)
{
    int i = blockIdx.x * blockDim.x + threadIdx.x;
    if (i >= N * 45) return;
    int n = i / 45, c = i - n * 45;
    float4 v = make_float4(0.f, 0.f, 0.f, 0.f);
    if (c < F4) v = x[(size_t)n * F4 + c];
    h[i] = v;
}

__global__ void zero_kernel(float4* __restrict__ p, int n4)
{
    int i = blockIdx.x * blockDim.x + threadIdx.x;
    if (i < n4) p[i] = make_float4(0.f, 0.f, 0.f, 0.f);
}

__global__ void scatter_kernel(const float* __restrict__ msg, const int* __restrict__ ei,
                               float* __restrict__ agg, int E)
{
    int i = blockIdx.x * blockDim.x + threadIdx.x;
    if (i >= E * 45) return;
    int e = i / 45, c = i - e * 45;
    int src = ei[e];
    int dst = ei[E + e];
    float4 v = reinterpret_cast<const float4*>(msg + (size_t)src * CCH)[c];
    float* p = agg + (size_t)dst * CCH + c * 4;
    asm volatile("red.global.add.v4.f32 [%0], {%1,%2,%3,%4};"
                 :: "l"(p), "f"(v.x), "f"(v.y), "f"(v.z), "f"(v.w) : "memory");
}

__global__ void count_kernel(const int* __restrict__ batch, float* __restrict__ cnt, int N)
{
    int i = blockIdx.x * blockDim.x + threadIdx.x;
    if (i < N) atomicAdd(&cnt[batch[i]], 1.f);
}

__global__ void pool_kernel(const float4* __restrict__ h, const int* __restrict__ batch,
                            float* __restrict__ pool, int comp, int N)
{
    int i = blockIdx.x * blockDim.x + threadIdx.x;
    if (i >= N * 45) return;
    int n = i / 45, c = i - n * 45;
    float4 v = h[i];
    v.x = fmaxf(v.x, 0.f); v.y = fmaxf(v.y, 0.f);
    v.z = fmaxf(v.z, 0.f); v.w = fmaxf(v.w, 0.f);
    float* p = pool + (size_t)batch[n] * FCD + comp * CCH + c * 4;
    asm volatile("red.global.add.v4.f32 [%0], {%1,%2,%3,%4};"
                 :: "l"(p), "f"(v.x), "f"(v.y), "f"(v.z), "f"(v.w) : "memory");
}

__global__ void bn_kernel(const float* __restrict__ pool, const float* __restrict__ cnt,
                          const float* __restrict__ gamma, const float* __restrict__ beta,
                          const float* __restrict__ mean, const float* __restrict__ var,
                          float* __restrict__ xout)
{
    int i = blockIdx.x * blockDim.x + threadIdx.x;
    if (i >= NGR * FCD) return;
    int b = i / FCD, j = i - b * FCD;
    int comp = j / CCH;
    float cn = fmaxf(cnt[comp * NGR + b], 1.f);
    float v = pool[i] / cn;
    v = (v - mean[j]) * rsqrtf(var[j] + 1e-5f) * gamma[j] + beta[j];
    xout[i] = v;
}

// ---------------- host orchestration ----------------
static inline void launch_gemm_nn(const float* A, const float* B, float* C,
                                  int N, int K, int M, int lda, cudaStream_t s)
{
    dim3 grid((N + 127) / 128, (M + 63) / 64);
    gemm_tf32<0, 0, 0><<<grid, 256, 0, s>>>(A, B, nullptr, C, N, K, M, lda);
}
template<int RELU>
static inline void launch_gemm_nt_bias(const float* A, const float* B, const float* bias,
                                       float* C, int N, int K, int M, cudaStream_t s)
{
    dim3 grid((N + 127) / 128, (M + 63) / 64);
    gemm_tf32<1, RELU, 1><<<grid, 256, 0, s>>>(A, B, bias, C, N, K, M, K);
}

extern "C" void kernel_launch(void* const* d_in, const int* in_sizes, int n_in,
                              void* d_out, int out_size)
{
    cudaStream_t s = 0;

    const float* x[3]     = {(const float*)d_in[0], (const float*)d_in[3], (const float*)d_in[6]};
    const int*   ei[3]    = {(const int*)d_in[1], (const int*)d_in[4], (const int*)d_in[7]};
    const int*   batch[3] = {(const int*)d_in[2], (const int*)d_in[5], (const int*)d_in[8]};
    const float* convW = (const float*)d_in[9];
    const float* Wih   = (const float*)d_in[10];
    const float* Whh   = (const float*)d_in[11];
    const float* bih   = (const float*)d_in[12];
    const float* bhh   = (const float*)d_in[13];
    const float* bn_g  = (const float*)d_in[14];
    const float* bn_b  = (const float*)d_in[15];
    const float* bn_m  = (const float*)d_in[16];
    const float* bn_v  = (const float*)d_in[17];
    const float* fc1W  = (const float*)d_in[18];
    const float* fc1b  = (const float*)d_in[19];
    const float* fc2W  = (const float*)d_in[20];
    const float* fc2b  = (const float*)d_in[21];
    const float* fc25W = (const float*)d_in[22];
    const float* fc25b = (const float*)d_in[23];
    const float* fc3W  = (const float*)d_in[24];
    const float* fc3b  = (const float*)d_in[25];

    const int N = in_sizes[2];          // nodes per component (50000)
    const int E = in_sizes[1] / 2;      // edges (150000)
    const int F = in_sizes[0] / N;      // input feat dim (64)

    float *h_, *hn_, *m_, *agg_, *pool_, *cnt_, *x_, *b1_, *b2_, *wtf_;
    cudaGetSymbolAddress((void**)&h_,   g_h);
    cudaGetSymbolAddress((void**)&hn_,  g_hn);
    cudaGetSymbolAddress((void**)&m_,   g_m);
    cudaGetSymbolAddress((void**)&agg_, g_agg);
    cudaGetSymbolAddress((void**)&pool_,g_pool);
    cudaGetSymbolAddress((void**)&cnt_, g_cnt);
    cudaGetSymbolAddress((void**)&x_,   g_x);
    cudaGetSymbolAddress((void**)&b1_,  g_b1);
    cudaGetSymbolAddress((void**)&b2_,  g_b2);
    cudaGetSymbolAddress((void**)&wtf_, g_wtf);

    // allow 128KB dynamic smem for the fused kernel
    cudaFuncSetAttribute(gru_fused, cudaFuncAttributeMaxDynamicSharedMemorySize, 131072);

    const int TPB = 256;
    const int nNC4 = N * 45;
    const int gNC4 = (nNC4 + TPB - 1) / TPB;
    const int gScat = (E * 45 + TPB - 1) / TPB;

    // pre-convert all weights to tf32
    {
        struct { const float* src; int off; int n; } wl[7] = {
            {convW, OFF_CONV, 3 * LNUM * CCH * CCH},
            {Wih,   OFF_WIH,  3 * FCD * CCH},
            {Whh,   OFF_WHH,  3 * FCD * CCH},
            {fc1W,  OFF_FC1,  HID * FCD},
            {fc2W,  OFF_FC2,  HID * HID},
            {fc25W, OFF_FC25, FCD * HID},
            {fc3W,  OFF_FC3,  3 * FCD},
        };
        for (int i = 0; i < 7; i++)
            cvt_tf32_kernel<<<(wl[i].n + 511) / 512, 512, 0, s>>>(wl[i].src, wtf_ + wl[i].off, wl[i].n);
    }

    zero_kernel<<<(NGR * FCD / 4 + TPB - 1) / TPB, TPB, 0, s>>>((float4*)pool_, NGR * FCD / 4);
    zero_kernel<<<(3 * NGR / 4 + TPB - 1) / TPB, TPB, 0, s>>>((float4*)cnt_, 3 * NGR / 4);

    const dim3 gruGrid((N + 63) / 64, 3);

    for (int comp = 0; comp < 3; comp++) {
        float* hcur = h_;
        float* hnext = hn_;
        pad_kernel<<<gNC4, TPB, 0, s>>>((const float4*)x[comp], (float4*)hcur, N, F / 4);
        const float* WihC = wtf_ + OFF_WIH + (size_t)comp * FCD * CCH;
        const float* WhhC = wtf_ + OFF_WHH + (size_t)comp * FCD * CCH;
        const float* bihC = bih + (size_t)comp * FCD;
        const float* bhhC = bhh + (size_t)comp * FCD;

        for (int l = 0; l < LNUM; l++) {
            const float* Wl = wtf_ + OFF_CONV + ((size_t)comp * LNUM + l) * CCH * CCH;
            int Keff = (l == 0 && (F % 4) == 0 && F < CCH) ? F : CCH;
            // m = hcur @ Wl  (layer 0: only first F k-rows are nonzero)
            launch_gemm_nn(hcur, Wl, m_, N, Keff, CCH, CCH, s);
            // agg = scatter_add(m[src] -> dst)
            zero_kernel<<<gNC4, TPB, 0, s>>>((float4*)agg_, nNC4);
            scatter_kernel<<<gScat, TPB, 0, s>>>(m_, ei[comp], agg_, E);
            // fused: gi/gh GEMMs + GRU gate, writes hnext
            gru_fused<<<gruGrid, 256, 131072, s>>>(agg_, hcur, WihC, WhhC, bihC, bhhC, hnext, N);
            float* t = hcur; hcur = hnext; hnext = t;
        }
        count_kernel<<<(N + TPB - 1) / TPB, TPB, 0, s>>>(batch[comp], cnt_ + comp * NGR, N);
        pool_kernel<<<gNC4, TPB, 0, s>>>((const float4*)hcur, batch[comp], pool_, comp, N);
    }

    bn_kernel<<<(NGR * FCD + TPB - 1) / TPB, TPB, 0, s>>>(pool_, cnt_, bn_g, bn_b, bn_m, bn_v, x_);

    // MLP head
    launch_gemm_nt_bias<1>(x_,  wtf_ + OFF_FC1,  fc1b,  b1_, NGR, FCD, HID, s);
    launch_gemm_nt_bias<1>(b1_, wtf_ + OFF_FC2,  fc2b,  b2_, NGR, HID, HID, s);
    launch_gemm_nt_bias<1>(b2_, wtf_ + OFF_FC25, fc25b, x_,  NGR, HID, FCD, s);
    launch_gemm_nt_bias<0>(x_,  wtf_ + OFF_FC3,  fc3b,  (float*)d_out, NGR, FCD, 3, s);
}

// round 6
// speedup vs baseline: 3.9065x; 1.0243x over previous
#include <cuda_runtime.h>
#include <cuda_bf16.h>
#include <math.h>
#include <stdint.h>

#define CCH 180
#define FCD 540           // 3*C
#define HID 1620          // 3*FC
#define NGR 2048
#define LNUM 6
#define MAXN 50000
#define MAXE 150000

// ---------------- scratch (device globals; no allocation allowed) ----------------
__device__ float g_h  [3][MAXN * CCH];
__device__ float g_hn [3][MAXN * CCH];
__device__ float g_m  [3][MAXN * CCH];
__device__ float g_agg[3][MAXN * CCH];
__device__ float g_pool[NGR * FCD];
__device__ float g_cnt [3 * NGR];
__device__ float g_x  [NGR * FCD];
__device__ float g_b1 [NGR * HID];
__device__ float g_b2 [NGR * HID];

// pre-converted (tf32-rounded) weights
#define OFF_CONV 0
#define OFF_WIH  972000
#define OFF_WHH  1263600
#define OFF_FC1  1555200
#define OFF_FC2  2430000
#define OFF_FC25 5054400
#define OFF_FC3  5929200
#define WTF_TOTAL 5930820
__device__ float g_wtf[WTF_TOTAL];

// ---------------- tf32 helpers ----------------
__device__ __forceinline__ uint32_t f2tf32(float f) {
    uint32_t u;
    asm("cvt.rna.tf32.f32 %0, %1;" : "=r"(u) : "f"(f));
    return u;
}

__device__ __forceinline__ void mma_tf32(float* c, const uint32_t* a, const uint32_t* b) {
    asm volatile(
        "mma.sync.aligned.m16n8k8.row.col.f32.tf32.tf32.f32 "
        "{%0,%1,%2,%3}, {%4,%5,%6,%7}, {%8,%9}, {%0,%1,%2,%3};"
        : "+f"(c[0]), "+f"(c[1]), "+f"(c[2]), "+f"(c[3])
        : "r"(a[0]), "r"(a[1]), "r"(a[2]), "r"(a[3]), "r"(b[0]), "r"(b[1]));
}

__device__ __forceinline__ void ldsm_x4(uint32_t& r0, uint32_t& r1, uint32_t& r2, uint32_t& r3,
                                        uint32_t saddr) {
    asm volatile("ldmatrix.sync.aligned.m8n8.x4.shared.b16 {%0,%1,%2,%3}, [%4];"
                 : "=r"(r0), "=r"(r1), "=r"(r2), "=r"(r3) : "r"(saddr));
}

__device__ __forceinline__ void cp_async16(uint32_t saddr, const void* gptr, int src_bytes) {
    asm volatile("cp.async.cg.shared.global [%0], [%1], 16, %2;"
                 :: "r"(saddr), "l"(gptr), "r"(src_bytes));
}
__device__ __forceinline__ void cp_commit() { asm volatile("cp.async.commit_group;"); }
__device__ __forceinline__ void cp_wait0()  { asm volatile("cp.async.wait_group 0;"); }

__device__ __forceinline__ float sigm(float x) { return 1.f / (1.f + __expf(-x)); }

// ---------------- generic tf32 tensor-core GEMM ----------------
// C[n,m] = sum_k A[n,k(lda)] * (TRANSB ? B[m,k] : B[k,m])  (+bias[m]) (+relu)
template<int TRANSB, int RELU, int BIAS>
__global__ __launch_bounds__(256)
void gemm_tf32(const float* __restrict__ A, const float* __restrict__ B,
               const float* __restrict__ bias, float* __restrict__ C,
               int N, int K, int M, int lda)
{
    __shared__ uint4 As4[2][128 * 8];
    __shared__ uint4 Bs4[2][64 * 8];

    const int tid  = threadIdx.x;
    const int lane = tid & 31;
    const int wid  = tid >> 5;
    const int wm   = (wid & 1) * 64;
    const int wn   = (wid >> 1) * 16;
    const int n0   = blockIdx.x * 128;
    const int m0   = blockIdx.y * 64;

    float acc[4][2][4];
    #pragma unroll
    for (int i = 0; i < 4; i++)
        #pragma unroll
        for (int j = 0; j < 2; j++)
            #pragma unroll
            for (int q = 0; q < 4; q++) acc[i][j][q] = 0.f;

    const int arow = tid >> 1;
    const int ac0  = (tid & 1) * 4;
    const bool arow_ok = (n0 + arow) < N;
    const float* Ap = A + (size_t)(n0 + arow) * lda;

    float4 pa[4];
    float4 pbnn[2];

    auto loadA = [&](int k0) {
        #pragma unroll
        for (int c = 0; c < 4; c++) {
            int gk = k0 + (ac0 + c) * 4;
            pa[c] = make_float4(0.f, 0.f, 0.f, 0.f);
            if (arow_ok && gk < K)
                pa[c] = *reinterpret_cast<const float4*>(Ap + gk);
        }
    };
    auto storeA = [&](int st) {
        #pragma unroll
        for (int c = 0; c < 4; c++) {
            int kc = ac0 + c;
            uint4 u;
            u.x = f2tf32(pa[c].x); u.y = f2tf32(pa[c].y);
            u.z = f2tf32(pa[c].z); u.w = f2tf32(pa[c].w);
            As4[st][(arow << 3) + (kc ^ (arow & 7))] = u;
        }
    };

    auto issueB_nt = [&](int k0, int st) {
        uint32_t sb = (uint32_t)__cvta_generic_to_shared(&Bs4[st][0]);
        #pragma unroll
        for (int i = 0; i < 2; i++) {
            int cid = tid * 2 + i;
            int m  = cid >> 3;
            int kc = cid & 7;
            int gm = m0 + m, gk = k0 + kc * 4;
            const float* gp = B + (size_t)gm * K + gk;
            int ok = (gm < M && gk < K) ? 16 : 0;
            cp_async16(sb + (((m << 3) + (kc ^ (m & 7))) << 4), gp, ok);
        }
    };
    auto loadB_nn = [&](int k0) {
        #pragma unroll
        for (int i = 0; i < 2; i++) {
            int s = tid + i * 256;
            int kc = s >> 6, m = s & 63;
            int gm = m0 + m;
            float* d = &pbnn[i].x;
            #pragma unroll
            for (int q = 0; q < 4; q++) {
                int gk = k0 + kc * 4 + q;
                d[q] = (gm < M && gk < K) ? B[(size_t)gk * M + gm] : 0.f;
            }
        }
    };
    auto storeB_nn = [&](int st) {
        #pragma unroll
        for (int i = 0; i < 2; i++) {
            int s = tid + i * 256;
            int kc = s >> 6, m = s & 63;
            uint4 u;
            u.x = __float_as_uint(pbnn[i].x); u.y = __float_as_uint(pbnn[i].y);
            u.z = __float_as_uint(pbnn[i].z); u.w = __float_as_uint(pbnn[i].w);
            Bs4[st][(m << 3) + (kc ^ (m & 7))] = u;
        }
    };

    const int g  = lane >> 3;
    const int l7 = lane & 7;

    auto compute = [&](int st) {
        uint32_t aBase = (uint32_t)__cvta_generic_to_shared(&As4[st][0]);
        uint32_t bBase = (uint32_t)__cvta_generic_to_shared(&Bs4[st][0]);
        #pragma unroll
        for (int kb = 0; kb < 32; kb += 8) {
            const int kq = kb >> 2;
            uint32_t a[4][4];
            #pragma unroll
            for (int i = 0; i < 4; i++) {
                int row = wm + i * 16 + ((g & 1) << 3) + l7;
                int kc  = kq + (g >> 1);
                uint32_t ad = aBase + (((row << 3) + (kc ^ (row & 7))) << 4);
                ldsm_x4(a[i][0], a[i][1], a[i][2], a[i][3], ad);
            }
            uint32_t b[4];
            {
                int nrow = wn + ((g >> 1) << 3) + l7;
                int kc   = kq + (g & 1);
                uint32_t bd = bBase + (((nrow << 3) + (kc ^ (nrow & 7))) << 4);
                ldsm_x4(b[0], b[1], b[2], b[3], bd);
            }
            #pragma unroll
            for (int i = 0; i < 4; i++) {
                mma_tf32(acc[i][0], a[i], &b[0]);
                mma_tf32(acc[i][1], a[i], &b[2]);
            }
        }
    };

    const int T = (K + 31) / 32;

    loadA(0);
    if (TRANSB) issueB_nt(0, 0); else loadB_nn(0);
    storeA(0);
    if (!TRANSB) storeB_nn(0);
    if (TRANSB) { cp_commit(); cp_wait0(); }
    __syncthreads();

    for (int kt = 0; kt < T; kt++) {
        const int cur = kt & 1, nxt = cur ^ 1;
        const bool more = (kt + 1) < T;
        if (more) {
            loadA((kt + 1) * 32);
            if (TRANSB) { issueB_nt((kt + 1) * 32, nxt); cp_commit(); }
            else loadB_nn((kt + 1) * 32);
        }
        compute(cur);
        if (more) {
            storeA(nxt);
            if (!TRANSB) storeB_nn(nxt);
            if (TRANSB) cp_wait0();
            __syncthreads();
        }
    }

    #pragma unroll
    for (int i = 0; i < 4; i++) {
        #pragma unroll
        for (int j = 0; j < 2; j++) {
            int r0 = n0 + wm + i * 16 + (lane >> 2);
            int c0 = m0 + wn + j * 8 + (lane & 3) * 2;
            if (c0 >= M) continue;
            bool c1ok = (c0 + 1) < M;
            float bv0 = BIAS ? bias[c0] : 0.f;
            float bv1 = (BIAS && c1ok) ? bias[c0 + 1] : 0.f;
            #pragma unroll
            for (int hrow = 0; hrow < 2; hrow++) {
                int r = r0 + hrow * 8;
                if (r >= N) continue;
                float v0 = acc[i][j][hrow * 2 + 0] + bv0;
                float v1 = acc[i][j][hrow * 2 + 1] + bv1;
                if (RELU) { v0 = fmaxf(v0, 0.f); v1 = fmaxf(v1, 0.f); }
                if (c1ok && ((M & 1) == 0)) {
                    *reinterpret_cast<float2*>(C + (size_t)r * M + c0) = make_float2(v0, v1);
                } else {
                    C[(size_t)r * M + c0] = v0;
                    if (c1ok) C[(size_t)r * M + c0 + 1] = v1;
                }
            }
        }
    }
}

// ---------------- fused GRU kernel (gi/gh GEMMs + gate epilogue) ----------------
__global__ __launch_bounds__(256, 1)
void gru_fused(const float* __restrict__ Aagg, const float* __restrict__ Ah,
               const float* __restrict__ Wih, const float* __restrict__ Whh,
               const float* __restrict__ bih, const float* __restrict__ bhh,
               float* __restrict__ hnew, int N)
{
    extern __shared__ uint4 sm[];
    const int tid  = threadIdx.x;
    const int lane = tid & 31;
    const int wid  = tid >> 5;
    const int wm   = (wid & 1) * 32;
    const int wn   = (wid >> 1) * 16;
    const int n0   = blockIdx.x * 64;
    const int m0   = blockIdx.y * 64;

    float acc_i[3][2][2][4];
    float acc_h[3][2][2][4];
    #pragma unroll
    for (int gi = 0; gi < 3; gi++)
        #pragma unroll
        for (int i = 0; i < 2; i++)
            #pragma unroll
            for (int j = 0; j < 2; j++)
                #pragma unroll
                for (int q = 0; q < 4; q++) { acc_i[gi][i][j][q] = 0.f; acc_h[gi][i][j][q] = 0.f; }

    const int arow = tid >> 2;
    const int ac0  = (tid & 3) * 2;
    const bool arow_ok = (n0 + arow) < N;
    const float* Aggp = Aagg + (size_t)(n0 + arow) * CCH;
    const float* Ahp  = Ah   + (size_t)(n0 + arow) * CCH;

    float4 pagg[2], ph[2];

    auto loadA = [&](int k0) {
        #pragma unroll
        for (int c = 0; c < 2; c++) {
            int gk = k0 + (ac0 + c) * 4;
            pagg[c] = make_float4(0.f, 0.f, 0.f, 0.f);
            ph[c]   = make_float4(0.f, 0.f, 0.f, 0.f);
            if (arow_ok && gk < CCH) {
                pagg[c] = *reinterpret_cast<const float4*>(Aggp + gk);
                ph[c]   = *reinterpret_cast<const float4*>(Ahp + gk);
            }
        }
    };
    auto storeA = [&](int st) {
        uint4* Sa = sm + st * 4096;
        uint4* Sh = Sa + 512;
        #pragma unroll
        for (int c = 0; c < 2; c++) {
            int kc = ac0 + c;
            int idx = (arow << 3) + (kc ^ (arow & 7));
            uint4 u;
            u.x = f2tf32(pagg[c].x); u.y = f2tf32(pagg[c].y);
            u.z = f2tf32(pagg[c].z); u.w = f2tf32(pagg[c].w);
            Sa[idx] = u;
            u.x = f2tf32(ph[c].x); u.y = f2tf32(ph[c].y);
            u.z = f2tf32(ph[c].z); u.w = f2tf32(ph[c].w);
            Sh[idx] = u;
        }
    };
    auto issueB = [&](int k0, int st) {
        uint32_t sb = (uint32_t)__cvta_generic_to_shared(sm + st * 4096 + 1024);
        #pragma unroll
        for (int mat = 0; mat < 6; mat++) {
            const float* W = (mat < 3) ? Wih : Whh;
            int goff = (mat % 3) * CCH;
            #pragma unroll
            for (int j = 0; j < 2; j++) {
                int cid = tid * 2 + j;
                int row = cid >> 3, kc = cid & 7;
                int gm = m0 + row;
                int gk = k0 + kc * 4;
                const float* gp = W + (size_t)(goff + gm) * CCH + gk;
                int ok = (gm < CCH && gk < CCH) ? 16 : 0;
                cp_async16(sb + ((mat * 512 + (row << 3) + (kc ^ (row & 7))) << 4), gp, ok);
            }
        }
    };

    const int g  = lane >> 3;
    const int l7 = lane & 7;

    auto compute = [&](int st) {
        uint32_t aBase = (uint32_t)__cvta_generic_to_shared(sm + st * 4096);
        uint32_t hBase = aBase + 512 * 16;
        uint32_t bBase = aBase + 1024 * 16;
        #pragma unroll
        for (int kb = 0; kb < 32; kb += 8) {
            const int kq = kb >> 2;
            uint32_t ag[2][4], ah[2][4];
            #pragma unroll
            for (int i = 0; i < 2; i++) {
                int row = wm + i * 16 + ((g & 1) << 3) + l7;
                int kc  = kq + (g >> 1);
                uint32_t off = ((row << 3) + (kc ^ (row & 7))) << 4;
                ldsm_x4(ag[i][0], ag[i][1], ag[i][2], ag[i][3], aBase + off);
                ldsm_x4(ah[i][0], ah[i][1], ah[i][2], ah[i][3], hBase + off);
            }
            uint32_t b[6][4];
            {
                int nrow = wn + ((g >> 1) << 3) + l7;
                int kc   = kq + (g & 1);
                uint32_t off = ((nrow << 3) + (kc ^ (nrow & 7))) << 4;
                #pragma unroll
                for (int mat = 0; mat < 6; mat++)
                    ldsm_x4(b[mat][0], b[mat][1], b[mat][2], b[mat][3],
                            bBase + (mat * 512 << 4) + off);
            }
            #pragma unroll
            for (int gi = 0; gi < 3; gi++)
                #pragma unroll
                for (int i = 0; i < 2; i++) {
                    mma_tf32(acc_i[gi][i][0], ag[i], &b[gi][0]);
                    mma_tf32(acc_i[gi][i][1], ag[i], &b[gi][2]);
                    mma_tf32(acc_h[gi][i][0], ah[i], &b[3 + gi][0]);
                    mma_tf32(acc_h[gi][i][1], ah[i], &b[3 + gi][2]);
                }
        }
    };

    const int T = (CCH + 31) / 32;

    loadA(0); issueB(0, 0);
    storeA(0);
    cp_commit(); cp_wait0();
    __syncthreads();

    for (int kt = 0; kt < T; kt++) {
        const int cur = kt & 1, nxt = cur ^ 1;
        const bool more = (kt + 1) < T;
        if (more) {
            loadA((kt + 1) * 32);
            issueB((kt + 1) * 32, nxt);
            cp_commit();
        }
        compute(cur);
        if (more) {
            storeA(nxt);
            cp_wait0();
            __syncthreads();
        }
    }

    #pragma unroll
    for (int i = 0; i < 2; i++) {
        #pragma unroll
        for (int j = 0; j < 2; j++) {
            int rbase = n0 + wm + i * 16 + (lane >> 2);
            int c0 = m0 + wn + j * 8 + (lane & 3) * 2;
            #pragma unroll
            for (int q = 0; q < 2; q++) {
                int r = rbase + q * 8;
                if (r >= N) continue;
                #pragma unroll
                for (int p = 0; p < 2; p++) {
                    int c = c0 + p;
                    if (c >= CCH) continue;
                    int v = q * 2 + p;
                    float ir = acc_i[0][i][j][v] + bih[c];
                    float iz = acc_i[1][i][j][v] + bih[c + CCH];
                    float in = acc_i[2][i][j][v] + bih[c + 2 * CCH];
                    float hr = acc_h[0][i][j][v] + bhh[c];
                    float hz = acc_h[1][i][j][v] + bhh[c + CCH];
                    float hn = acc_h[2][i][j][v] + bhh[c + 2 * CCH];
                    float rg = sigm(ir + hr);
                    float z  = sigm(iz + hz);
                    float nn = tanhf(in + rg * hn);
                    float ho = Ah[(size_t)r * CCH + c];
                    hnew[(size_t)r * CCH + c] = (1.f - z) * nn + z * ho;
                }
            }
        }
    }
}

// ---------------- weight pre-conversion ----------------
__global__ void cvt_tf32_kernel(const float* __restrict__ in, float* __restrict__ out, int n)
{
    int i = blockIdx.x * blockDim.x + threadIdx.x;
    if (i < n) out[i] = __uint_as_float(f2tf32(in[i]));
}

// ---------------- elementwise / graph kernels ----------------
__global__ void pad_kernel(const float4* __restrict__ x, float4* __restrict__ h, int N, int F4)
{
    int i = blockIdx.x * blockDim.x + threadIdx.x;
    if (i >= N * 45) return;
    int n = i / 45, c = i - n * 45;
    float4 v = make_float4(0.f, 0.f, 0.f, 0.f);
    if (c < F4) v = x[(size_t)n * F4 + c];
    h[i] = v;
}

__global__ void zero_kernel(float4* __restrict__ p, int n4)
{
    int i = blockIdx.x * blockDim.x + threadIdx.x;
    if (i < n4) p[i] = make_float4(0.f, 0.f, 0.f, 0.f);
}

__global__ void scatter_kernel(const float* __restrict__ msg, const int* __restrict__ ei,
                               float* __restrict__ agg, int E)
{
    int i = blockIdx.x * blockDim.x + threadIdx.x;
    if (i >= E * 45) return;
    int e = i / 45, c = i - e * 45;
    int src = ei[e];
    int dst = ei[E + e];
    float4 v = reinterpret_cast<const float4*>(msg + (size_t)src * CCH)[c];
    float* p = agg + (size_t)dst * CCH + c * 4;
    asm volatile("red.global.add.v4.f32 [%0], {%1,%2,%3,%4};"
                 :: "l"(p), "f"(v.x), "f"(v.y), "f"(v.z), "f"(v.w) : "memory");
}

__global__ void count_kernel(const int* __restrict__ batch, float* __restrict__ cnt, int N)
{
    int i = blockIdx.x * blockDim.x + threadIdx.x;
    if (i < N) atomicAdd(&cnt[batch[i]], 1.f);
}

__global__ void pool_kernel(const float4* __restrict__ h, const int* __restrict__ batch,
                            float* __restrict__ pool, int comp, int N)
{
    int i = blockIdx.x * blockDim.x + threadIdx.x;
    if (i >= N * 45) return;
    int n = i / 45, c = i - n * 45;
    float4 v = h[i];
    v.x = fmaxf(v.x, 0.f); v.y = fmaxf(v.y, 0.f);
    v.z = fmaxf(v.z, 0.f); v.w = fmaxf(v.w, 0.f);
    float* p = pool + (size_t)batch[n] * FCD + comp * CCH + c * 4;
    asm volatile("red.global.add.v4.f32 [%0], {%1,%2,%3,%4};"
                 :: "l"(p), "f"(v.x), "f"(v.y), "f"(v.z), "f"(v.w) : "memory");
}

__global__ void bn_kernel(const float* __restrict__ pool, const float* __restrict__ cnt,
                          const float* __restrict__ gamma, const float* __restrict__ beta,
                          const float* __restrict__ mean, const float* __restrict__ var,
                          float* __restrict__ xout)
{
    int i = blockIdx.x * blockDim.x + threadIdx.x;
    if (i >= NGR * FCD) return;
    int b = i / FCD, j = i - b * FCD;
    int comp = j / CCH;
    float cn = fmaxf(cnt[comp * NGR + b], 1.f);
    float v = pool[i] / cn;
    v = (v - mean[j]) * rsqrtf(var[j] + 1e-5f) * gamma[j] + beta[j];
    xout[i] = v;
}

// ---------------- host orchestration ----------------
static inline void launch_gemm_nn(const float* A, const float* B, float* C,
                                  int N, int K, int M, int lda, cudaStream_t s)
{
    dim3 grid((N + 127) / 128, (M + 63) / 64);
    gemm_tf32<0, 0, 0><<<grid, 256, 0, s>>>(A, B, nullptr, C, N, K, M, lda);
}
template<int RELU>
static inline void launch_gemm_nt_bias(const float* A, const float* B, const float* bias,
                                       float* C, int N, int K, int M, cudaStream_t s)
{
    dim3 grid((N + 127) / 128, (M + 63) / 64);
    gemm_tf32<1, RELU, 1><<<grid, 256, 0, s>>>(A, B, bias, C, N, K, M, K);
}

extern "C" void kernel_launch(void* const* d_in, const int* in_sizes, int n_in,
                              void* d_out, int out_size)
{
    // streams/events: created on first call (the non-captured correctness run);
    // reused identically on every call — same work every time.
    static cudaStream_t cs[3] = {0, 0, 0};
    static cudaEvent_t ev_root = 0, ev_done[3] = {0, 0, 0};
    if (cs[0] == 0) {
        for (int i = 0; i < 3; i++) {
            cudaStreamCreateWithFlags(&cs[i], cudaStreamNonBlocking);
            cudaEventCreateWithFlags(&ev_done[i], cudaEventDisableTiming);
        }
        cudaEventCreateWithFlags(&ev_root, cudaEventDisableTiming);
        cudaFuncSetAttribute(gru_fused, cudaFuncAttributeMaxDynamicSharedMemorySize, 131072);
    }
    cudaStream_t s0 = 0;

    const float* x[3]     = {(const float*)d_in[0], (const float*)d_in[3], (const float*)d_in[6]};
    const int*   ei[3]    = {(const int*)d_in[1], (const int*)d_in[4], (const int*)d_in[7]};
    const int*   batch[3] = {(const int*)d_in[2], (const int*)d_in[5], (const int*)d_in[8]};
    const float* convW = (const float*)d_in[9];
    const float* Wih   = (const float*)d_in[10];
    const float* Whh   = (const float*)d_in[11];
    const float* bih   = (const float*)d_in[12];
    const float* bhh   = (const float*)d_in[13];
    const float* bn_g  = (const float*)d_in[14];
    const float* bn_b  = (const float*)d_in[15];
    const float* bn_m  = (const float*)d_in[16];
    const float* bn_v  = (const float*)d_in[17];
    const float* fc1b  = (const float*)d_in[19];
    const float* fc2b  = (const float*)d_in[21];
    const float* fc25b = (const float*)d_in[23];
    const float* fc3b  = (const float*)d_in[25];

    const int N = in_sizes[2];
    const int E = in_sizes[1] / 2;
    const int F = in_sizes[0] / N;

    float *h_, *hn_, *m_, *agg_, *pool_, *cnt_, *x_, *b1_, *b2_, *wtf_;
    cudaGetSymbolAddress((void**)&h_,   g_h);
    cudaGetSymbolAddress((void**)&hn_,  g_hn);
    cudaGetSymbolAddress((void**)&m_,   g_m);
    cudaGetSymbolAddress((void**)&agg_, g_agg);
    cudaGetSymbolAddress((void**)&pool_,g_pool);
    cudaGetSymbolAddress((void**)&cnt_, g_cnt);
    cudaGetSymbolAddress((void**)&x_,   g_x);
    cudaGetSymbolAddress((void**)&b1_,  g_b1);
    cudaGetSymbolAddress((void**)&b2_,  g_b2);
    cudaGetSymbolAddress((void**)&wtf_, g_wtf);

    const int TPB = 256;
    const int nNC4 = N * 45;
    const int gNC4 = (nNC4 + TPB - 1) / TPB;
    const int gScat = (E * 45 + TPB - 1) / TPB;

    // pre-convert all weights to tf32 (on root stream)
    {
        const float* fc1W  = (const float*)d_in[18];
        const float* fc2W  = (const float*)d_in[20];
        const float* fc25W = (const float*)d_in[22];
        const float* fc3W  = (const float*)d_in[24];
        struct { const float* src; int off; int n; } wl[7] = {
            {convW, OFF_CONV, 3 * LNUM * CCH * CCH},
            {Wih,   OFF_WIH,  3 * FCD * CCH},
            {Whh,   OFF_WHH,  3 * FCD * CCH},
            {fc1W,  OFF_FC1,  HID * FCD},
            {fc2W,  OFF_FC2,  HID * HID},
            {fc25W, OFF_FC25, FCD * HID},
            {fc3W,  OFF_FC3,  3 * FCD},
        };
        for (int i = 0; i < 7; i++)
            cvt_tf32_kernel<<<(wl[i].n + 511) / 512, 512, 0, s0>>>(wl[i].src, wtf_ + wl[i].off, wl[i].n);
    }

    zero_kernel<<<(NGR * FCD / 4 + TPB - 1) / TPB, TPB, 0, s0>>>((float4*)pool_, NGR * FCD / 4);
    zero_kernel<<<(3 * NGR / 4 + TPB - 1) / TPB, TPB, 0, s0>>>((float4*)cnt_, 3 * NGR / 4);

    // fork
    cudaEventRecord(ev_root, s0);

    const dim3 gruGrid((N + 63) / 64, 3);
    const size_t CS = (size_t)MAXN * CCH;   // per-component scratch stride

    for (int comp = 0; comp < 3; comp++) {
        cudaStream_t s = cs[comp];
        cudaStreamWaitEvent(s, ev_root, 0);

        float* hcur  = h_  + comp * CS;
        float* hnext = hn_ + comp * CS;
        float* mm    = m_  + comp * CS;
        float* ag    = agg_ + comp * CS;

        pad_kernel<<<gNC4, TPB, 0, s>>>((const float4*)x[comp], (float4*)hcur, N, F / 4);
        const float* WihC = wtf_ + OFF_WIH + (size_t)comp * FCD * CCH;
        const float* WhhC = wtf_ + OFF_WHH + (size_t)comp * FCD * CCH;
        const float* bihC = bih + (size_t)comp * FCD;
        const float* bhhC = bhh + (size_t)comp * FCD;

        for (int l = 0; l < LNUM; l++) {
            const float* Wl = wtf_ + OFF_CONV + ((size_t)comp * LNUM + l) * CCH * CCH;
            int Keff = (l == 0 && (F % 4) == 0 && F < CCH) ? F : CCH;
            launch_gemm_nn(hcur, Wl, mm, N, Keff, CCH, CCH, s);
            zero_kernel<<<gNC4, TPB, 0, s>>>((float4*)ag, nNC4);
            scatter_kernel<<<gScat, TPB, 0, s>>>(mm, ei[comp], ag, E);
            gru_fused<<<gruGrid, 256, 131072, s>>>(ag, hcur, WihC, WhhC, bihC, bhhC, hnext, N);
            float* t = hcur; hcur = hnext; hnext = t;
        }
        count_kernel<<<(N + TPB - 1) / TPB, TPB, 0, s>>>(batch[comp], cnt_ + comp * NGR, N);
        pool_kernel<<<gNC4, TPB, 0, s>>>((const float4*)hcur, batch[comp], pool_, comp, N);
        cudaEventRecord(ev_done[comp], s);
    }

    // join
    for (int comp = 0; comp < 3; comp++)
        cudaStreamWaitEvent(s0, ev_done[comp], 0);

    bn_kernel<<<(NGR * FCD + TPB - 1) / TPB, TPB, 0, s0>>>(pool_, cnt_, bn_g, bn_b, bn_m, bn_v, x_);

    launch_gemm_nt_bias<1>(x_,  wtf_ + OFF_FC1,  fc1b,  b1_, NGR, FCD, HID, s0);
    launch_gemm_nt_bias<1>(b1_, wtf_ + OFF_FC2,  fc2b,  b2_, NGR, HID, HID, s0);
    launch_gemm_nt_bias<1>(b2_, wtf_ + OFF_FC25, fc25b, x_,  NGR, HID, FCD, s0);
    launch_gemm_nt_bias<0>(x_,  wtf_ + OFF_FC3,  fc3b,  (float*)d_out, NGR, FCD, 3, s0);
}